// round 4
// baseline (speedup 1.0000x reference)
#include <cuda_runtime.h>
#include <cuda_bf16.h>
#include <math.h>
#include <stdint.h>

#define NB 512
#define NL 64
#define ND 1024
#define NU 512
#define NROWS (NB * NL)   // 32768 feature rows

// ---------------------------------------------------------------------------
// Device-global scratch (no allocation allowed)
// ---------------------------------------------------------------------------
__device__ __align__(1024) __nv_bfloat16 g_fhi[(size_t)NROWS * ND];  // 64 MB
__device__ __align__(1024) __nv_bfloat16 g_flo[(size_t)NROWS * ND];  // 64 MB
__device__ __align__(1024) __nv_bfloat16 g_W1Th[(size_t)NU * ND];    // [N=512][K=1024]
__device__ __align__(1024) __nv_bfloat16 g_W1Tl[(size_t)NU * ND];
__device__ float g_h[NB * NU];           // hidden @ W2 + b2
__device__ float g_lp[4 * NROWS];        // per-N-block partial logits

// ---------------------------------------------------------------------------
// PTX helpers (sm_80-era: valid on plain sm_103 target)
// ---------------------------------------------------------------------------
__device__ __forceinline__ uint32_t smem_u32(const void* p) {
    uint32_t a;
    asm("{ .reg .u64 t; cvta.to.shared.u64 t, %1; cvt.u32.u64 %0, t; }" : "=r"(a) : "l"(p));
    return a;
}
__device__ __forceinline__ void cp_async16(uint32_t dst, const void* src) {
    asm volatile("cp.async.cg.shared.global [%0], [%1], 16;" :: "r"(dst), "l"(src) : "memory");
}
__device__ __forceinline__ void cp_commit() {
    asm volatile("cp.async.commit_group;" ::: "memory");
}
template <int N> __device__ __forceinline__ void cp_wait() {
    asm volatile("cp.async.wait_group %0;" :: "n"(N) : "memory");
}
__device__ __forceinline__ void ldsm_x4(uint32_t* r, uint32_t addr) {
    asm volatile("ldmatrix.sync.aligned.m8n8.x4.shared.b16 {%0,%1,%2,%3}, [%4];"
                 : "=r"(r[0]), "=r"(r[1]), "=r"(r[2]), "=r"(r[3]) : "r"(addr));
}
__device__ __forceinline__ void mma_bf16(float* c, const uint32_t* a, const uint32_t* b) {
    asm volatile(
        "mma.sync.aligned.m16n8k16.row.col.f32.bf16.bf16.f32 "
        "{%0,%1,%2,%3}, {%4,%5,%6,%7}, {%8,%9}, {%0,%1,%2,%3};"
        : "+f"(c[0]), "+f"(c[1]), "+f"(c[2]), "+f"(c[3])
        : "r"(a[0]), "r"(a[1]), "r"(a[2]), "r"(a[3]), "r"(b[0]), "r"(b[1]));
}

// fast tanh: 1 - 2/(exp2(2*log2e*x)+1); rel err ~1e-6. Saturates correctly.
__device__ __forceinline__ float tanh_fast(float x) {
    float e;
    asm("ex2.approx.f32 %0, %1;" : "=f"(e) : "f"(x * 2.88539008177792681f));
    float r;
    asm("rcp.approx.f32 %0, %1;" : "=f"(r) : "f"(e + 1.0f));
    return 1.0f - 2.0f * r;
}

// ---------------------------------------------------------------------------
// kconvA: features fp32 -> (hi, lo) bf16 split. 4 elements per thread.
// ---------------------------------------------------------------------------
__global__ __launch_bounds__(256) void kconvA(const float* __restrict__ X)
{
    size_t i = ((size_t)blockIdx.x * 256 + threadIdx.x) * 4;
    float4 v = *(const float4*)(X + i);
    float a[4] = {v.x, v.y, v.z, v.w};
    uint32_t ph[2], pl[2];
    #pragma unroll
    for (int j = 0; j < 2; ++j) {
        __nv_bfloat16 h0 = __float2bfloat16(a[2*j]);
        __nv_bfloat16 h1 = __float2bfloat16(a[2*j+1]);
        __nv_bfloat16 l0 = __float2bfloat16(a[2*j]   - __bfloat162float(h0));
        __nv_bfloat16 l1 = __float2bfloat16(a[2*j+1] - __bfloat162float(h1));
        ph[j] = (uint32_t)__bfloat16_as_ushort(h0) | ((uint32_t)__bfloat16_as_ushort(h1) << 16);
        pl[j] = (uint32_t)__bfloat16_as_ushort(l0) | ((uint32_t)__bfloat16_as_ushort(l1) << 16);
    }
    *(uint2*)((char*)g_fhi + i * 2) = make_uint2(ph[0], ph[1]);
    *(uint2*)((char*)g_flo + i * 2) = make_uint2(pl[0], pl[1]);
}

// ---------------------------------------------------------------------------
// kconvW: W1 [K=1024, N=512] fp32 -> W1T hi/lo [N=512][K=1024] bf16
// ---------------------------------------------------------------------------
__global__ __launch_bounds__(256) void kconvW(const float* __restrict__ W1)
{
    __shared__ float t[32][33];
    int n0 = blockIdx.x * 32, k0 = blockIdx.y * 32;
    int tx = threadIdx.x & 31, ty = threadIdx.x >> 5;   // 32 x 8
    #pragma unroll
    for (int i = 0; i < 32; i += 8)
        t[ty + i][tx] = W1[(size_t)(k0 + ty + i) * NU + n0 + tx];
    __syncthreads();
    #pragma unroll
    for (int i = 0; i < 32; i += 8) {
        float v = t[tx][ty + i];                 // = W1[k0+tx][n0+ty+i]
        __nv_bfloat16 h = __float2bfloat16(v);
        size_t idx = (size_t)(n0 + ty + i) * ND + k0 + tx;
        g_W1Th[idx] = h;
        g_W1Tl[idx] = __float2bfloat16(v - __bfloat162float(h));
    }
}

// ---------------------------------------------------------------------------
// k1: h = hidden @ W2 + b2   (512x512x512, fp32 SIMT)
// ---------------------------------------------------------------------------
__global__ __launch_bounds__(256) void k1_hidden_gemm(
    const float* __restrict__ hidden, const float* __restrict__ W2,
    const float* __restrict__ b2)
{
    const int tid = threadIdx.x;
    const int tx = tid & 15, ty = tid >> 4;
    const int rowB = blockIdx.x * 64;
    const int nB   = blockIdx.y * 64;

    __shared__ float Xs[16][64];
    __shared__ float Ws[16][68];
    float acc[4][4] = {};

    for (int k0 = 0; k0 < NU; k0 += 16) {
        {
            int r = tid >> 2, c4 = (tid & 3) * 4;
            float4 v = *(const float4*)(hidden + (size_t)(rowB + r) * NU + k0 + c4);
            Xs[c4 + 0][r] = v.x; Xs[c4 + 1][r] = v.y;
            Xs[c4 + 2][r] = v.z; Xs[c4 + 3][r] = v.w;
        }
        {
            int k = tid >> 4, c4 = (tid & 15) * 4;
            *(float4*)&Ws[k][c4] = *(const float4*)(W2 + (size_t)(k0 + k) * NU + nB + c4);
        }
        __syncthreads();
        #pragma unroll
        for (int k = 0; k < 16; ++k) {
            float4 a = *(const float4*)&Xs[k][ty * 4];
            float4 b = *(const float4*)&Ws[k][tx * 4];
            float am[4] = {a.x, a.y, a.z, a.w};
            float bn[4] = {b.x, b.y, b.z, b.w};
            #pragma unroll
            for (int i = 0; i < 4; ++i)
                #pragma unroll
                for (int j = 0; j < 4; ++j)
                    acc[i][j] = fmaf(am[i], bn[j], acc[i][j]);
        }
        __syncthreads();
    }
    #pragma unroll
    for (int i = 0; i < 4; ++i)
        #pragma unroll
        for (int j = 0; j < 4; ++j)
            g_h[(size_t)(rowB + ty * 4 + i) * NU + nB + tx * 4 + j] =
                acc[i][j] + b2[nB + tx * 4 + j];
}

// ---------------------------------------------------------------------------
// k2: bf16 mma.sync GEMM, 3x split (AhBh + AlBh + AhBl), fused epilogue.
// BM=128, BN=128, BK=32, 512 threads (16 warps: 4M x 4N, warp tile 32x32),
// 3-stage cp.async. SMEM rows padded to 80B -> ldmatrix conflict-free.
// ---------------------------------------------------------------------------
#define ROWB 80
#define TILE_B (128 * ROWB)      // 10240 bytes per tile
#define STG_B  (4 * TILE_B)      // Ah, Al, Wh, Wl
#define STAGES 3
#define HS_OFF   (STAGES * STG_B)          // 2 x 128 floats
#define VS_OFF   (HS_OFF + 1024)           // 128 floats
#define PART_OFF (VS_OFF + 512)            // 128 x 4 floats
#define SMEM_K2  (PART_OFF + 2048)

__global__ __launch_bounds__(512) void k2_score_gemm(
    const float* __restrict__ b1, const float* __restrict__ Vw)
{
    extern __shared__ __align__(1024) char smem[];
    const uint32_t sb = smem_u32(smem);
    const int tid  = threadIdx.x;
    const int lane = tid & 31, wid = tid >> 5;
    const int wm = wid >> 2, wn = wid & 3;     // 4 x 4 warp grid
    const int rowB = blockIdx.x * 128;
    const int nB   = blockIdx.y * 128;

    float* hs   = (float*)(smem + HS_OFF);    // [2][128]
    float* Vs   = (float*)(smem + VS_OFF);    // [128]
    float* part = (float*)(smem + PART_OFF);  // [128][4]

    // epilogue constants
    if (tid < 256) {
        int bloc = tid >> 7, c = tid & 127;
        hs[tid] = g_h[(size_t)(blockIdx.x * 2 + bloc) * NU + nB + c] + b1[nB + c];
        if (tid < 128) Vs[tid] = Vw[nB + tid];
    }

    const __nv_bfloat16* base0 = g_fhi  + (size_t)rowB * ND;
    const __nv_bfloat16* base1 = g_flo  + (size_t)rowB * ND;
    const __nv_bfloat16* base2 = g_W1Th + (size_t)nB   * ND;
    const __nv_bfloat16* base3 = g_W1Tl + (size_t)nB   * ND;

    // stage loader: 2048 x 16B chunks, 4 per thread
    auto load_stage = [&](int s, int kc) {
        uint32_t sdst = sb + s * STG_B;
        #pragma unroll
        for (int i = 0; i < 4; ++i) {
            int idx  = tid + i * 512;
            int tile = idx >> 9;
            int rem  = idx & 511;
            int row  = rem >> 2, ch = rem & 3;
            const __nv_bfloat16* gb =
                (tile == 0) ? base0 : (tile == 1) ? base1 : (tile == 2) ? base2 : base3;
            cp_async16(sdst + tile * TILE_B + row * ROWB + ch * 16,
                       gb + (size_t)row * ND + kc * 32 + ch * 8);
        }
        cp_commit();
    };

    // prologue: fill 3 stages
    load_stage(0, 0);
    load_stage(1, 1);
    load_stage(2, 2);

    float acc[2][4][4] = {};    // [mt 16-row][nt 8-col][vals]

    // precomputed ldmatrix intra-warp offsets
    const int a_row = ((lane >> 3) & 1) * 8 + (lane & 7);
    const int a_ch  = (lane >> 4);
    const int b_row = (lane >> 4) * 8 + (lane & 7);
    const int b_ch  = ((lane >> 3) & 1);

    for (int c = 0; c < ND / 32; ++c) {
        int s = c % STAGES;
        cp_wait<STAGES - 1>();
        __syncthreads();

        uint32_t ahB = sb + s * STG_B;
        uint32_t alB = ahB + TILE_B;
        uint32_t whB = ahB + 2 * TILE_B;
        uint32_t wlB = ahB + 3 * TILE_B;

        #pragma unroll
        for (int kk = 0; kk < 2; ++kk) {
            uint32_t ah[2][4], al[2][4], bh[4][2], bl[4][2];
            #pragma unroll
            for (int mt = 0; mt < 2; ++mt) {
                int r  = wm * 32 + mt * 16 + a_row;
                int ch = kk * 2 + a_ch;
                ldsm_x4(ah[mt], ahB + r * ROWB + ch * 16);
                ldsm_x4(al[mt], alB + r * ROWB + ch * 16);
            }
            #pragma unroll
            for (int ntp = 0; ntp < 2; ++ntp) {
                int r  = wn * 32 + ntp * 16 + b_row;
                int ch = kk * 2 + b_ch;
                uint32_t t0[4], t1[4];
                ldsm_x4(t0, whB + r * ROWB + ch * 16);
                ldsm_x4(t1, wlB + r * ROWB + ch * 16);
                bh[ntp*2][0] = t0[0]; bh[ntp*2][1] = t0[1];
                bh[ntp*2+1][0] = t0[2]; bh[ntp*2+1][1] = t0[3];
                bl[ntp*2][0] = t1[0]; bl[ntp*2][1] = t1[1];
                bl[ntp*2+1][0] = t1[2]; bl[ntp*2+1][1] = t1[3];
            }
            #pragma unroll
            for (int mt = 0; mt < 2; ++mt)
                #pragma unroll
                for (int nt = 0; nt < 4; ++nt) {
                    mma_bf16(acc[mt][nt], ah[mt], bh[nt]);
                    mma_bf16(acc[mt][nt], al[mt], bh[nt]);
                    mma_bf16(acc[mt][nt], ah[mt], bl[nt]);
                }
        }

        __syncthreads();
        if (c + STAGES < ND / 32) load_stage(s, c + STAGES);
        else cp_commit();   // keep wait_group counting consistent
    }

    // Fused epilogue: tanh(acc + b1 + h) . V  -> partial logits
    const int g = lane >> 2, tg4 = lane & 3;
    const int bloc = wm >> 1;
    #pragma unroll
    for (int mt = 0; mt < 2; ++mt) {
        float s0 = 0.f, s1 = 0.f;
        #pragma unroll
        for (int nt = 0; nt < 4; ++nt) {
            #pragma unroll
            for (int c2 = 0; c2 < 2; ++c2) {
                int col = wn * 32 + nt * 8 + tg4 * 2 + c2;
                float hb = hs[bloc * 128 + col];
                float vw = Vs[col];
                s0 = fmaf(tanh_fast(acc[mt][nt][c2]     + hb), vw, s0);
                s1 = fmaf(tanh_fast(acc[mt][nt][2 + c2] + hb), vw, s1);
            }
        }
        s0 += __shfl_xor_sync(0xFFFFFFFFu, s0, 1);
        s0 += __shfl_xor_sync(0xFFFFFFFFu, s0, 2);
        s1 += __shfl_xor_sync(0xFFFFFFFFu, s1, 1);
        s1 += __shfl_xor_sync(0xFFFFFFFFu, s1, 2);
        if (tg4 == 0) {
            int r0 = wm * 32 + mt * 16 + g;
            part[r0 * 4 + wn]       = s0;
            part[(r0 + 8) * 4 + wn] = s1;
        }
    }
    __syncthreads();
    if (tid < 128)
        g_lp[(size_t)blockIdx.y * NROWS + rowB + tid] =
            (part[tid*4] + part[tid*4+1]) + (part[tid*4+2] + part[tid*4+3]);
}

// ---------------------------------------------------------------------------
// k3: softmax over L=64 per batch (sums 4 N-block partials). Writes attn.
// ---------------------------------------------------------------------------
__global__ __launch_bounds__(256) void k3_softmax(float* __restrict__ out_attn)
{
    int b    = (blockIdx.x * 256 + threadIdx.x) >> 5;
    int lane = threadIdx.x & 31;

    float x1 = 0.f, x2 = 0.f;
    #pragma unroll
    for (int p = 0; p < 4; ++p) {
        x1 += g_lp[(size_t)p * NROWS + b * 64 + lane];
        x2 += g_lp[(size_t)p * NROWS + b * 64 + lane + 32];
    }
    float m = fmaxf(x1, x2);
    #pragma unroll
    for (int o = 16; o > 0; o >>= 1)
        m = fmaxf(m, __shfl_xor_sync(0xFFFFFFFFu, m, o));
    float e1 = expf(x1 - m), e2 = expf(x2 - m);
    float s = e1 + e2;
    #pragma unroll
    for (int o = 16; o > 0; o >>= 1)
        s += __shfl_xor_sync(0xFFFFFFFFu, s, o);
    float inv = 1.f / s;
    out_attn[b * 64 + lane]      = e1 * inv;
    out_attn[b * 64 + lane + 32] = e2 * inv;
}

// ---------------------------------------------------------------------------
// k4: context[b,d] = sum_l attn[b,l] * features[b,l,d]
// ---------------------------------------------------------------------------
__global__ __launch_bounds__(256) void k4_context(
    const float* __restrict__ X, const float* __restrict__ attn,
    float* __restrict__ ctx)
{
    int b = blockIdx.x;
    __shared__ float as[64];
    if (threadIdx.x < 64) as[threadIdx.x] = attn[b * 64 + threadIdx.x];
    __syncthreads();

    const float4* Xb = (const float4*)(X + (size_t)b * NL * ND);
    int c = threadIdx.x;
    float4 acc = make_float4(0.f, 0.f, 0.f, 0.f);
    #pragma unroll 8
    for (int l = 0; l < NL; ++l) {
        float a = as[l];
        float4 f = Xb[(size_t)l * 256 + c];
        acc.x = fmaf(a, f.x, acc.x);
        acc.y = fmaf(a, f.y, acc.y);
        acc.z = fmaf(a, f.z, acc.z);
        acc.w = fmaf(a, f.w, acc.w);
    }
    ((float4*)(ctx + (size_t)b * ND))[c] = acc;
}

// ---------------------------------------------------------------------------
extern "C" void kernel_launch(void* const* d_in, const int* in_sizes, int n_in,
                              void* d_out, int out_size)
{
    const float* features = (const float*)d_in[0];
    const float* hidden   = (const float*)d_in[1];
    const float* W1_w     = (const float*)d_in[2];
    const float* W1_b     = (const float*)d_in[3];
    const float* W2_w     = (const float*)d_in[4];
    const float* W2_b     = (const float*)d_in[5];
    const float* V_w      = (const float*)d_in[6];
    // d_in[7] = V_b: unused (softmax shift-invariant)

    float* out  = (float*)d_out;
    float* ctx  = out;
    float* attn = out + (size_t)NB * ND;

    cudaFuncSetAttribute(k2_score_gemm,
                         cudaFuncAttributeMaxDynamicSharedMemorySize, SMEM_K2);

    kconvW<<<dim3(NU / 32, ND / 32), 256>>>(W1_w);
    kconvA<<<(NROWS * ND) / 4 / 256, 256>>>(features);
    k1_hidden_gemm<<<dim3(NB / 64, NU / 64), 256>>>(hidden, W2_w, W2_b);
    k2_score_gemm<<<dim3(NROWS / 128, NU / 128), 512, SMEM_K2>>>(W1_b, V_w);
    k3_softmax<<<NB / 8, 256>>>(attn);
    k4_context<<<NB, 256>>>(features, attn, ctx);
}

// round 5
// speedup vs baseline: 1.1734x; 1.1734x over previous
#include <cuda_runtime.h>
#include <cuda_bf16.h>
#include <math.h>
#include <stdint.h>

#define NB 512
#define NL 64
#define ND 1024
#define NU 512
#define NROWS (NB * NL)   // 32768 feature rows

// ---------------------------------------------------------------------------
// Device-global scratch (no allocation allowed)
// ---------------------------------------------------------------------------
__device__ __align__(1024) __nv_bfloat16 g_fhi[(size_t)NROWS * ND];  // 64 MB
__device__ __align__(1024) __nv_bfloat16 g_flo[(size_t)NROWS * ND];  // 64 MB
__device__ __align__(1024) __nv_bfloat16 g_W1Th[(size_t)NU * ND];    // [N=512][K=1024]
__device__ __align__(1024) __nv_bfloat16 g_W1Tl[(size_t)NU * ND];
__device__ float g_h[NB * NU];           // hidden @ W2 + b2
__device__ float g_lp[4 * NROWS];        // per-N-block partial logits

// ---------------------------------------------------------------------------
// PTX helpers (sm_80-era: valid on plain sm_103 target)
// ---------------------------------------------------------------------------
__device__ __forceinline__ uint32_t smem_u32(const void* p) {
    uint32_t a;
    asm("{ .reg .u64 t; cvta.to.shared.u64 t, %1; cvt.u32.u64 %0, t; }" : "=r"(a) : "l"(p));
    return a;
}
__device__ __forceinline__ void cp_async16(uint32_t dst, const void* src) {
    asm volatile("cp.async.cg.shared.global [%0], [%1], 16;" :: "r"(dst), "l"(src) : "memory");
}
__device__ __forceinline__ void cp_commit() {
    asm volatile("cp.async.commit_group;" ::: "memory");
}
template <int N> __device__ __forceinline__ void cp_wait() {
    asm volatile("cp.async.wait_group %0;" :: "n"(N) : "memory");
}
__device__ __forceinline__ void ldsm_x4(uint32_t* r, uint32_t addr) {
    asm volatile("ldmatrix.sync.aligned.m8n8.x4.shared.b16 {%0,%1,%2,%3}, [%4];"
                 : "=r"(r[0]), "=r"(r[1]), "=r"(r[2]), "=r"(r[3]) : "r"(addr));
}
__device__ __forceinline__ void mma_bf16(float* c, const uint32_t* a, const uint32_t* b) {
    asm volatile(
        "mma.sync.aligned.m16n8k16.row.col.f32.bf16.bf16.f32 "
        "{%0,%1,%2,%3}, {%4,%5,%6,%7}, {%8,%9}, {%0,%1,%2,%3};"
        : "+f"(c[0]), "+f"(c[1]), "+f"(c[2]), "+f"(c[3])
        : "r"(a[0]), "r"(a[1]), "r"(a[2]), "r"(a[3]), "r"(b[0]), "r"(b[1]));
}

// fast tanh: 1 - 2/(exp2(2*log2e*x)+1); rel err ~1e-6. Saturates correctly.
__device__ __forceinline__ float tanh_fast(float x) {
    float e;
    asm("ex2.approx.f32 %0, %1;" : "=f"(e) : "f"(x * 2.88539008177792681f));
    float r;
    asm("rcp.approx.f32 %0, %1;" : "=f"(r) : "f"(e + 1.0f));
    return 1.0f - 2.0f * r;
}

// ---------------------------------------------------------------------------
// kconvA: features fp32 -> (hi, lo) bf16 split. 4 elements per thread.
// ---------------------------------------------------------------------------
__global__ __launch_bounds__(256) void kconvA(const float* __restrict__ X)
{
    size_t i = ((size_t)blockIdx.x * 256 + threadIdx.x) * 4;
    float4 v = *(const float4*)(X + i);
    float a[4] = {v.x, v.y, v.z, v.w};
    uint32_t ph[2], pl[2];
    #pragma unroll
    for (int j = 0; j < 2; ++j) {
        __nv_bfloat16 h0 = __float2bfloat16(a[2*j]);
        __nv_bfloat16 h1 = __float2bfloat16(a[2*j+1]);
        __nv_bfloat16 l0 = __float2bfloat16(a[2*j]   - __bfloat162float(h0));
        __nv_bfloat16 l1 = __float2bfloat16(a[2*j+1] - __bfloat162float(h1));
        ph[j] = (uint32_t)__bfloat16_as_ushort(h0) | ((uint32_t)__bfloat16_as_ushort(h1) << 16);
        pl[j] = (uint32_t)__bfloat16_as_ushort(l0) | ((uint32_t)__bfloat16_as_ushort(l1) << 16);
    }
    *(uint2*)((char*)g_fhi + i * 2) = make_uint2(ph[0], ph[1]);
    *(uint2*)((char*)g_flo + i * 2) = make_uint2(pl[0], pl[1]);
}

// ---------------------------------------------------------------------------
// kconvW: W1 [K=1024, N=512] fp32 -> W1T hi/lo [N=512][K=1024] bf16
// ---------------------------------------------------------------------------
__global__ __launch_bounds__(256) void kconvW(const float* __restrict__ W1)
{
    __shared__ float t[32][33];
    int n0 = blockIdx.x * 32, k0 = blockIdx.y * 32;
    int tx = threadIdx.x & 31, ty = threadIdx.x >> 5;   // 32 x 8
    #pragma unroll
    for (int i = 0; i < 32; i += 8)
        t[ty + i][tx] = W1[(size_t)(k0 + ty + i) * NU + n0 + tx];
    __syncthreads();
    #pragma unroll
    for (int i = 0; i < 32; i += 8) {
        float v = t[tx][ty + i];                 // = W1[k0+tx][n0+ty+i]
        __nv_bfloat16 h = __float2bfloat16(v);
        size_t idx = (size_t)(n0 + ty + i) * ND + k0 + tx;
        g_W1Th[idx] = h;
        g_W1Tl[idx] = __float2bfloat16(v - __bfloat162float(h));
    }
}

// ---------------------------------------------------------------------------
// k1: h = hidden @ W2 + b2   (512x512x512, fp32 SIMT)
// ---------------------------------------------------------------------------
__global__ __launch_bounds__(256) void k1_hidden_gemm(
    const float* __restrict__ hidden, const float* __restrict__ W2,
    const float* __restrict__ b2)
{
    const int tid = threadIdx.x;
    const int tx = tid & 15, ty = tid >> 4;
    const int rowB = blockIdx.x * 64;
    const int nB   = blockIdx.y * 64;

    __shared__ float Xs[16][64];
    __shared__ float Ws[16][68];
    float acc[4][4] = {};

    for (int k0 = 0; k0 < NU; k0 += 16) {
        {
            int r = tid >> 2, c4 = (tid & 3) * 4;
            float4 v = *(const float4*)(hidden + (size_t)(rowB + r) * NU + k0 + c4);
            Xs[c4 + 0][r] = v.x; Xs[c4 + 1][r] = v.y;
            Xs[c4 + 2][r] = v.z; Xs[c4 + 3][r] = v.w;
        }
        {
            int k = tid >> 4, c4 = (tid & 15) * 4;
            *(float4*)&Ws[k][c4] = *(const float4*)(W2 + (size_t)(k0 + k) * NU + nB + c4);
        }
        __syncthreads();
        #pragma unroll
        for (int k = 0; k < 16; ++k) {
            float4 a = *(const float4*)&Xs[k][ty * 4];
            float4 b = *(const float4*)&Ws[k][tx * 4];
            float am[4] = {a.x, a.y, a.z, a.w};
            float bn[4] = {b.x, b.y, b.z, b.w};
            #pragma unroll
            for (int i = 0; i < 4; ++i)
                #pragma unroll
                for (int j = 0; j < 4; ++j)
                    acc[i][j] = fmaf(am[i], bn[j], acc[i][j]);
        }
        __syncthreads();
    }
    #pragma unroll
    for (int i = 0; i < 4; ++i)
        #pragma unroll
        for (int j = 0; j < 4; ++j)
            g_h[(size_t)(rowB + ty * 4 + i) * NU + nB + tx * 4 + j] =
                acc[i][j] + b2[nB + tx * 4 + j];
}

// ---------------------------------------------------------------------------
// k2: bf16 mma.sync GEMM, 3x split (AhBh + AlBh + AhBl), fused epilogue.
// BM=128, BN=128, BK=32. 128 threads (4 warps: 2M x 2N, warp tile 64x64).
// 2-stage cp.async, 2 CTAs/SM (smem ~82KB). 80B rows: ldmatrix conflict-free.
// ---------------------------------------------------------------------------
#define ROWB 80
#define TILE_B (128 * ROWB)      // 10240 bytes per tile
#define STG_B  (4 * TILE_B)      // Ah, Al, Wh, Wl
#define STAGES 2
#define HS_OFF   (STAGES * STG_B)          // 2 x 128 floats
#define VS_OFF   (HS_OFF + 1024)           // 128 floats
#define PART_OFF (VS_OFF + 512)            // 128 x 2 floats
#define SMEM_K2  (PART_OFF + 1024)

__global__ __launch_bounds__(128, 2) void k2_score_gemm(
    const float* __restrict__ b1, const float* __restrict__ Vw)
{
    extern __shared__ __align__(1024) char smem[];
    const uint32_t sb = smem_u32(smem);
    const int tid  = threadIdx.x;
    const int lane = tid & 31, wid = tid >> 5;
    const int wm = wid >> 1, wn = wid & 1;     // 2 x 2 warp grid, 64x64 tiles
    const int rowB = blockIdx.x * 128;
    const int nB   = blockIdx.y * 128;

    float* hs   = (float*)(smem + HS_OFF);    // [2][128]
    float* Vs   = (float*)(smem + VS_OFF);    // [128]
    float* part = (float*)(smem + PART_OFF);  // [128][2]

    // epilogue constants (2 per thread)
    {
        int i0 = tid, i1 = tid + 128;
        hs[i0] = g_h[(size_t)(blockIdx.x * 2) * NU + nB + i0] + b1[nB + i0];
        hs[i1] = g_h[(size_t)(blockIdx.x * 2 + 1) * NU + nB + (i1 - 128)] + b1[nB + (i1 - 128)];
        Vs[tid] = Vw[nB + tid];
    }

    const __nv_bfloat16* base0 = g_fhi  + (size_t)rowB * ND;
    const __nv_bfloat16* base1 = g_flo  + (size_t)rowB * ND;
    const __nv_bfloat16* base2 = g_W1Th + (size_t)nB   * ND;
    const __nv_bfloat16* base3 = g_W1Tl + (size_t)nB   * ND;

    // stage loader: 2048 x 16B chunks, 16 per thread
    auto load_stage = [&](int s, int kc) {
        uint32_t sdst = sb + s * STG_B;
        #pragma unroll
        for (int i = 0; i < 16; ++i) {
            int idx  = tid + i * 128;
            int tile = idx >> 9;               // 512 chunks per tile
            int rem  = idx & 511;
            int row  = rem >> 2, ch = rem & 3;
            const __nv_bfloat16* gb =
                (tile == 0) ? base0 : (tile == 1) ? base1 : (tile == 2) ? base2 : base3;
            cp_async16(sdst + tile * TILE_B + row * ROWB + ch * 16,
                       gb + (size_t)row * ND + kc * 32 + ch * 8);
        }
        cp_commit();
    };

    // prologue: fill 2 stages
    load_stage(0, 0);
    load_stage(1, 1);

    float acc[4][8][4] = {};    // [mt 16-row][nt 8-col][vals]

    // precomputed ldmatrix intra-warp offsets
    const int a_row = ((lane >> 3) & 1) * 8 + (lane & 7);
    const int a_ch  = (lane >> 4);
    const int b_row = (lane >> 4) * 8 + (lane & 7);
    const int b_ch  = ((lane >> 3) & 1);

    for (int c = 0; c < ND / 32; ++c) {
        int s = c & 1;
        cp_wait<STAGES - 1>();
        __syncthreads();

        uint32_t ahB = sb + s * STG_B;
        uint32_t alB = ahB + TILE_B;
        uint32_t whB = ahB + 2 * TILE_B;
        uint32_t wlB = ahB + 3 * TILE_B;

        #pragma unroll
        for (int kk = 0; kk < 2; ++kk) {
            uint32_t ah[4][4], al[4][4], bh[8][2], bl[8][2];
            #pragma unroll
            for (int mt = 0; mt < 4; ++mt) {
                int r  = wm * 64 + mt * 16 + a_row;
                int ch = kk * 2 + a_ch;
                ldsm_x4(ah[mt], ahB + r * ROWB + ch * 16);
                ldsm_x4(al[mt], alB + r * ROWB + ch * 16);
            }
            #pragma unroll
            for (int ntp = 0; ntp < 4; ++ntp) {
                int r  = wn * 64 + ntp * 16 + b_row;
                int ch = kk * 2 + b_ch;
                uint32_t t0[4], t1[4];
                ldsm_x4(t0, whB + r * ROWB + ch * 16);
                ldsm_x4(t1, wlB + r * ROWB + ch * 16);
                bh[ntp*2][0] = t0[0]; bh[ntp*2][1] = t0[1];
                bh[ntp*2+1][0] = t0[2]; bh[ntp*2+1][1] = t0[3];
                bl[ntp*2][0] = t1[0]; bl[ntp*2][1] = t1[1];
                bl[ntp*2+1][0] = t1[2]; bl[ntp*2+1][1] = t1[3];
            }
            #pragma unroll
            for (int mt = 0; mt < 4; ++mt)
                #pragma unroll
                for (int nt = 0; nt < 8; ++nt) {
                    mma_bf16(acc[mt][nt], ah[mt], bh[nt]);
                    mma_bf16(acc[mt][nt], al[mt], bh[nt]);
                    mma_bf16(acc[mt][nt], ah[mt], bl[nt]);
                }
        }

        __syncthreads();
        if (c + STAGES < ND / 32) load_stage(s, c + STAGES);
        else cp_commit();   // keep wait_group counting consistent
    }

    // Fused epilogue: tanh(acc + b1 + h) . V  -> partial logits
    const int g = lane >> 2, tg4 = lane & 3;
    const int bloc = wm;               // warp tile 64 rows == one batch (L=64)
    #pragma unroll
    for (int mt = 0; mt < 4; ++mt) {
        float s0 = 0.f, s1 = 0.f;
        #pragma unroll
        for (int nt = 0; nt < 8; ++nt) {
            #pragma unroll
            for (int c2 = 0; c2 < 2; ++c2) {
                int col = wn * 64 + nt * 8 + tg4 * 2 + c2;
                float hb = hs[bloc * 128 + col];
                float vw = Vs[col];
                s0 = fmaf(tanh_fast(acc[mt][nt][c2]     + hb), vw, s0);
                s1 = fmaf(tanh_fast(acc[mt][nt][2 + c2] + hb), vw, s1);
            }
        }
        s0 += __shfl_xor_sync(0xFFFFFFFFu, s0, 1);
        s0 += __shfl_xor_sync(0xFFFFFFFFu, s0, 2);
        s1 += __shfl_xor_sync(0xFFFFFFFFu, s1, 1);
        s1 += __shfl_xor_sync(0xFFFFFFFFu, s1, 2);
        if (tg4 == 0) {
            int r0 = wm * 64 + mt * 16 + g;
            part[r0 * 2 + wn]       = s0;
            part[(r0 + 8) * 2 + wn] = s1;
        }
    }
    __syncthreads();
    g_lp[(size_t)blockIdx.y * NROWS + rowB + tid] = part[tid*2] + part[tid*2+1];
}

// ---------------------------------------------------------------------------
// k3: softmax over L=64 per batch (sums 4 N-block partials). Writes attn.
// ---------------------------------------------------------------------------
__global__ __launch_bounds__(256) void k3_softmax(float* __restrict__ out_attn)
{
    int b    = (blockIdx.x * 256 + threadIdx.x) >> 5;
    int lane = threadIdx.x & 31;

    float x1 = 0.f, x2 = 0.f;
    #pragma unroll
    for (int p = 0; p < 4; ++p) {
        x1 += g_lp[(size_t)p * NROWS + b * 64 + lane];
        x2 += g_lp[(size_t)p * NROWS + b * 64 + lane + 32];
    }
    float m = fmaxf(x1, x2);
    #pragma unroll
    for (int o = 16; o > 0; o >>= 1)
        m = fmaxf(m, __shfl_xor_sync(0xFFFFFFFFu, m, o));
    float e1 = expf(x1 - m), e2 = expf(x2 - m);
    float s = e1 + e2;
    #pragma unroll
    for (int o = 16; o > 0; o >>= 1)
        s += __shfl_xor_sync(0xFFFFFFFFu, s, o);
    float inv = 1.f / s;
    out_attn[b * 64 + lane]      = e1 * inv;
    out_attn[b * 64 + lane + 32] = e2 * inv;
}

// ---------------------------------------------------------------------------
// k4: context[b,d] = sum_l attn[b,l] * features[b,l,d]
// ---------------------------------------------------------------------------
__global__ __launch_bounds__(256) void k4_context(
    const float* __restrict__ X, const float* __restrict__ attn,
    float* __restrict__ ctx)
{
    int b = blockIdx.x;
    __shared__ float as[64];
    if (threadIdx.x < 64) as[threadIdx.x] = attn[b * 64 + threadIdx.x];
    __syncthreads();

    const float4* Xb = (const float4*)(X + (size_t)b * NL * ND);
    int c = threadIdx.x;
    float4 acc = make_float4(0.f, 0.f, 0.f, 0.f);
    #pragma unroll 8
    for (int l = 0; l < NL; ++l) {
        float a = as[l];
        float4 f = Xb[(size_t)l * 256 + c];
        acc.x = fmaf(a, f.x, acc.x);
        acc.y = fmaf(a, f.y, acc.y);
        acc.z = fmaf(a, f.z, acc.z);
        acc.w = fmaf(a, f.w, acc.w);
    }
    ((float4*)(ctx + (size_t)b * ND))[c] = acc;
}

// ---------------------------------------------------------------------------
extern "C" void kernel_launch(void* const* d_in, const int* in_sizes, int n_in,
                              void* d_out, int out_size)
{
    const float* features = (const float*)d_in[0];
    const float* hidden   = (const float*)d_in[1];
    const float* W1_w     = (const float*)d_in[2];
    const float* W1_b     = (const float*)d_in[3];
    const float* W2_w     = (const float*)d_in[4];
    const float* W2_b     = (const float*)d_in[5];
    const float* V_w      = (const float*)d_in[6];
    // d_in[7] = V_b: unused (softmax shift-invariant)

    float* out  = (float*)d_out;
    float* ctx  = out;
    float* attn = out + (size_t)NB * ND;

    cudaFuncSetAttribute(k2_score_gemm,
                         cudaFuncAttributeMaxDynamicSharedMemorySize, SMEM_K2);

    kconvW<<<dim3(NU / 32, ND / 32), 256>>>(W1_w);
    kconvA<<<(NROWS * ND) / 4 / 256, 256>>>(features);
    k1_hidden_gemm<<<dim3(NB / 64, NU / 64), 256>>>(hidden, W2_w, W2_b);
    k2_score_gemm<<<dim3(NROWS / 128, NU / 128), 128, SMEM_K2>>>(W1_b, V_w);
    k3_softmax<<<NB / 8, 256>>>(attn);
    k4_context<<<NB, 256>>>(features, attn, ctx);
}

// round 6
// speedup vs baseline: 1.5544x; 1.3247x over previous
#include <cuda_runtime.h>
#include <cuda_fp16.h>
#include <math.h>
#include <stdint.h>

#define NB 512
#define NL 64
#define ND 1024
#define NU 512
#define NROWS (NB * NL)   // 32768 feature rows

// ---------------------------------------------------------------------------
// Device-global scratch (no allocation allowed)
// ---------------------------------------------------------------------------
__device__ __align__(1024) __half g_fa[(size_t)NROWS * ND];    // 64 MB, fp16 features
__device__ __align__(1024) __half g_W1Th[(size_t)NU * ND];     // [N=512][K=1024] hi
__device__ __align__(1024) __half g_W1Tl[(size_t)NU * ND];     // lo residual
__device__ float g_h[NB * NU];           // hidden @ W2 + b2
__device__ float g_lp[4 * NROWS];        // per-N-block partial logits

// ---------------------------------------------------------------------------
// PTX helpers (sm_80-era: valid on plain sm_103 target)
// ---------------------------------------------------------------------------
__device__ __forceinline__ uint32_t smem_u32(const void* p) {
    uint32_t a;
    asm("{ .reg .u64 t; cvta.to.shared.u64 t, %1; cvt.u32.u64 %0, t; }" : "=r"(a) : "l"(p));
    return a;
}
__device__ __forceinline__ void cp_async16(uint32_t dst, const void* src) {
    asm volatile("cp.async.cg.shared.global [%0], [%1], 16;" :: "r"(dst), "l"(src) : "memory");
}
__device__ __forceinline__ void cp_commit() {
    asm volatile("cp.async.commit_group;" ::: "memory");
}
template <int N> __device__ __forceinline__ void cp_wait() {
    asm volatile("cp.async.wait_group %0;" :: "n"(N) : "memory");
}
__device__ __forceinline__ void ldsm_x4(uint32_t* r, uint32_t addr) {
    asm volatile("ldmatrix.sync.aligned.m8n8.x4.shared.b16 {%0,%1,%2,%3}, [%4];"
                 : "=r"(r[0]), "=r"(r[1]), "=r"(r[2]), "=r"(r[3]) : "r"(addr));
}
__device__ __forceinline__ void mma_f16(float* c, const uint32_t* a, const uint32_t* b) {
    asm volatile(
        "mma.sync.aligned.m16n8k16.row.col.f32.f16.f16.f32 "
        "{%0,%1,%2,%3}, {%4,%5,%6,%7}, {%8,%9}, {%0,%1,%2,%3};"
        : "+f"(c[0]), "+f"(c[1]), "+f"(c[2]), "+f"(c[3])
        : "r"(a[0]), "r"(a[1]), "r"(a[2]), "r"(a[3]), "r"(b[0]), "r"(b[1]));
}

// fast tanh: 1 - 2/(exp2(2*log2e*x)+1); rel err ~1e-6. Saturates correctly.
__device__ __forceinline__ float tanh_fast(float x) {
    float e;
    asm("ex2.approx.f32 %0, %1;" : "=f"(e) : "f"(x * 2.88539008177792681f));
    float r;
    asm("rcp.approx.f32 %0, %1;" : "=f"(r) : "f"(e + 1.0f));
    return 1.0f - 2.0f * r;
}

// ---------------------------------------------------------------------------
// kconvA: features fp32 -> fp16 (single rounding). 4 elements per thread.
// ---------------------------------------------------------------------------
__global__ __launch_bounds__(256) void kconvA(const float* __restrict__ X)
{
    size_t i = ((size_t)blockIdx.x * 256 + threadIdx.x) * 4;
    float4 v = *(const float4*)(X + i);
    __half2 p0 = __floats2half2_rn(v.x, v.y);
    __half2 p1 = __floats2half2_rn(v.z, v.w);
    *(uint2*)((char*)g_fa + i * 2) =
        make_uint2(*(uint32_t*)&p0, *(uint32_t*)&p1);
}

// ---------------------------------------------------------------------------
// kconvW: W1 [K=1024, N=512] fp32 -> W1T hi/lo fp16 [N=512][K=1024]
// ---------------------------------------------------------------------------
__global__ __launch_bounds__(256) void kconvW(const float* __restrict__ W1)
{
    __shared__ float t[32][33];
    int n0 = blockIdx.x * 32, k0 = blockIdx.y * 32;
    int tx = threadIdx.x & 31, ty = threadIdx.x >> 5;   // 32 x 8
    #pragma unroll
    for (int i = 0; i < 32; i += 8)
        t[ty + i][tx] = W1[(size_t)(k0 + ty + i) * NU + n0 + tx];
    __syncthreads();
    #pragma unroll
    for (int i = 0; i < 32; i += 8) {
        float v = t[tx][ty + i];                 // = W1[k0+tx][n0+ty+i]
        __half h = __float2half_rn(v);
        size_t idx = (size_t)(n0 + ty + i) * ND + k0 + tx;
        g_W1Th[idx] = h;
        g_W1Tl[idx] = __float2half_rn(v - __half2float(h));
    }
}

// ---------------------------------------------------------------------------
// k1: h = hidden @ W2 + b2   (512x512x512, fp32 SIMT)
// ---------------------------------------------------------------------------
__global__ __launch_bounds__(256) void k1_hidden_gemm(
    const float* __restrict__ hidden, const float* __restrict__ W2,
    const float* __restrict__ b2)
{
    const int tid = threadIdx.x;
    const int tx = tid & 15, ty = tid >> 4;
    const int rowB = blockIdx.x * 64;
    const int nB   = blockIdx.y * 64;

    __shared__ float Xs[16][64];
    __shared__ float Ws[16][68];
    float acc[4][4] = {};

    for (int k0 = 0; k0 < NU; k0 += 16) {
        {
            int r = tid >> 2, c4 = (tid & 3) * 4;
            float4 v = *(const float4*)(hidden + (size_t)(rowB + r) * NU + k0 + c4);
            Xs[c4 + 0][r] = v.x; Xs[c4 + 1][r] = v.y;
            Xs[c4 + 2][r] = v.z; Xs[c4 + 3][r] = v.w;
        }
        {
            int k = tid >> 4, c4 = (tid & 15) * 4;
            *(float4*)&Ws[k][c4] = *(const float4*)(W2 + (size_t)(k0 + k) * NU + nB + c4);
        }
        __syncthreads();
        #pragma unroll
        for (int k = 0; k < 16; ++k) {
            float4 a = *(const float4*)&Xs[k][ty * 4];
            float4 b = *(const float4*)&Ws[k][tx * 4];
            float am[4] = {a.x, a.y, a.z, a.w};
            float bn[4] = {b.x, b.y, b.z, b.w};
            #pragma unroll
            for (int i = 0; i < 4; ++i)
                #pragma unroll
                for (int j = 0; j < 4; ++j)
                    acc[i][j] = fmaf(am[i], bn[j], acc[i][j]);
        }
        __syncthreads();
    }
    #pragma unroll
    for (int i = 0; i < 4; ++i)
        #pragma unroll
        for (int j = 0; j < 4; ++j)
            g_h[(size_t)(rowB + ty * 4 + i) * NU + nB + tx * 4 + j] =
                acc[i][j] + b2[nB + tx * 4 + j];
}

// ---------------------------------------------------------------------------
// k2: fp16 mma.sync GEMM, 2-term (A.Wh + A.Wl), fused epilogue.
// BM=128, BN=128, BK=32. 128 threads (4 warps: 2M x 2N, warp tile 64x64).
// 3-stage cp.async, 2 CTAs/SM (smem ~92KB). 80B rows: ldmatrix conflict-free.
// ---------------------------------------------------------------------------
#define ROWB 80
#define TILE_B (128 * ROWB)      // 10240 bytes per tile
#define STG_B  (3 * TILE_B)      // A, Wh, Wl
#define STAGES 3
#define HS_OFF   (STAGES * STG_B)          // 2 x 128 floats
#define VS_OFF   (HS_OFF + 1024)           // 128 floats
#define PART_OFF (VS_OFF + 512)            // 128 x 2 floats
#define SMEM_K2  (PART_OFF + 1024)

__global__ __launch_bounds__(128, 2) void k2_score_gemm(
    const float* __restrict__ b1, const float* __restrict__ Vw)
{
    extern __shared__ __align__(1024) char smem[];
    const uint32_t sb = smem_u32(smem);
    const int tid  = threadIdx.x;
    const int lane = tid & 31, wid = tid >> 5;
    const int wm = wid >> 1, wn = wid & 1;     // 2 x 2 warp grid, 64x64 tiles
    const int rowB = blockIdx.x * 128;
    const int nB   = blockIdx.y * 128;

    float* hs   = (float*)(smem + HS_OFF);    // [2][128]
    float* Vs   = (float*)(smem + VS_OFF);    // [128]
    float* part = (float*)(smem + PART_OFF);  // [128][2]

    // epilogue constants (2 per thread)
    {
        int i0 = tid, i1 = tid + 128;
        hs[i0] = g_h[(size_t)(blockIdx.x * 2) * NU + nB + i0] + b1[nB + i0];
        hs[i1] = g_h[(size_t)(blockIdx.x * 2 + 1) * NU + nB + (i1 - 128)] + b1[nB + (i1 - 128)];
        Vs[tid] = Vw[nB + tid];
    }

    const __half* base0 = g_fa   + (size_t)rowB * ND;
    const __half* base1 = g_W1Th + (size_t)nB   * ND;
    const __half* base2 = g_W1Tl + (size_t)nB   * ND;

    // stage loader: 1536 x 16B chunks, 12 per thread
    auto load_stage = [&](int s, int kc) {
        uint32_t sdst = sb + s * STG_B;
        #pragma unroll
        for (int i = 0; i < 12; ++i) {
            int idx  = tid + i * 128;
            int tile = idx >> 9;               // 512 chunks per tile
            int rem  = idx & 511;
            int row  = rem >> 2, ch = rem & 3;
            const __half* gb = (tile == 0) ? base0 : (tile == 1) ? base1 : base2;
            cp_async16(sdst + tile * TILE_B + row * ROWB + ch * 16,
                       gb + (size_t)row * ND + kc * 32 + ch * 8);
        }
        cp_commit();
    };

    // prologue: fill 3 stages
    load_stage(0, 0);
    load_stage(1, 1);
    load_stage(2, 2);

    float acc[4][8][4] = {};    // [mt 16-row][nt 8-col][vals]

    // precomputed ldmatrix intra-warp offsets
    const int a_row = ((lane >> 3) & 1) * 8 + (lane & 7);
    const int a_ch  = (lane >> 4);
    const int b_row = (lane >> 4) * 8 + (lane & 7);
    const int b_ch  = ((lane >> 3) & 1);

    for (int c = 0; c < ND / 32; ++c) {
        int s = c % STAGES;
        cp_wait<STAGES - 1>();
        __syncthreads();

        uint32_t aB  = sb + s * STG_B;
        uint32_t whB = aB + TILE_B;
        uint32_t wlB = aB + 2 * TILE_B;

        #pragma unroll
        for (int kk = 0; kk < 2; ++kk) {
            uint32_t a[4][4], bh[8][2], bl[8][2];
            #pragma unroll
            for (int mt = 0; mt < 4; ++mt) {
                int r  = wm * 64 + mt * 16 + a_row;
                int ch = kk * 2 + a_ch;
                ldsm_x4(a[mt], aB + r * ROWB + ch * 16);
            }
            #pragma unroll
            for (int ntp = 0; ntp < 4; ++ntp) {
                int r  = wn * 64 + ntp * 16 + b_row;
                int ch = kk * 2 + b_ch;
                uint32_t t0[4], t1[4];
                ldsm_x4(t0, whB + r * ROWB + ch * 16);
                ldsm_x4(t1, wlB + r * ROWB + ch * 16);
                bh[ntp*2][0] = t0[0]; bh[ntp*2][1] = t0[1];
                bh[ntp*2+1][0] = t0[2]; bh[ntp*2+1][1] = t0[3];
                bl[ntp*2][0] = t1[0]; bl[ntp*2][1] = t1[1];
                bl[ntp*2+1][0] = t1[2]; bl[ntp*2+1][1] = t1[3];
            }
            #pragma unroll
            for (int mt = 0; mt < 4; ++mt)
                #pragma unroll
                for (int nt = 0; nt < 8; ++nt) {
                    mma_f16(acc[mt][nt], a[mt], bh[nt]);
                    mma_f16(acc[mt][nt], a[mt], bl[nt]);
                }
        }

        __syncthreads();
        if (c + STAGES < ND / 32) load_stage(s, c + STAGES);
        else cp_commit();   // keep wait_group counting consistent
    }

    // Fused epilogue: tanh(acc + b1 + h) . V  -> partial logits
    const int g = lane >> 2, tg4 = lane & 3;
    const int bloc = wm;               // warp tile 64 rows == one batch (L=64)
    #pragma unroll
    for (int mt = 0; mt < 4; ++mt) {
        float s0 = 0.f, s1 = 0.f;
        #pragma unroll
        for (int nt = 0; nt < 8; ++nt) {
            #pragma unroll
            for (int c2 = 0; c2 < 2; ++c2) {
                int col = wn * 64 + nt * 8 + tg4 * 2 + c2;
                float hb = hs[bloc * 128 + col];
                float vw = Vs[col];
                s0 = fmaf(tanh_fast(acc[mt][nt][c2]     + hb), vw, s0);
                s1 = fmaf(tanh_fast(acc[mt][nt][2 + c2] + hb), vw, s1);
            }
        }
        s0 += __shfl_xor_sync(0xFFFFFFFFu, s0, 1);
        s0 += __shfl_xor_sync(0xFFFFFFFFu, s0, 2);
        s1 += __shfl_xor_sync(0xFFFFFFFFu, s1, 1);
        s1 += __shfl_xor_sync(0xFFFFFFFFu, s1, 2);
        if (tg4 == 0) {
            int r0 = wm * 64 + mt * 16 + g;
            part[r0 * 2 + wn]       = s0;
            part[(r0 + 8) * 2 + wn] = s1;
        }
    }
    __syncthreads();
    g_lp[(size_t)blockIdx.y * NROWS + rowB + tid] = part[tid*2] + part[tid*2+1];
}

// ---------------------------------------------------------------------------
// k3: softmax over L=64 per batch (sums 4 N-block partials). Writes attn.
// ---------------------------------------------------------------------------
__global__ __launch_bounds__(256) void k3_softmax(float* __restrict__ out_attn)
{
    int b    = (blockIdx.x * 256 + threadIdx.x) >> 5;
    int lane = threadIdx.x & 31;

    float x1 = 0.f, x2 = 0.f;
    #pragma unroll
    for (int p = 0; p < 4; ++p) {
        x1 += g_lp[(size_t)p * NROWS + b * 64 + lane];
        x2 += g_lp[(size_t)p * NROWS + b * 64 + lane + 32];
    }
    float m = fmaxf(x1, x2);
    #pragma unroll
    for (int o = 16; o > 0; o >>= 1)
        m = fmaxf(m, __shfl_xor_sync(0xFFFFFFFFu, m, o));
    float e1 = expf(x1 - m), e2 = expf(x2 - m);
    float s = e1 + e2;
    #pragma unroll
    for (int o = 16; o > 0; o >>= 1)
        s += __shfl_xor_sync(0xFFFFFFFFu, s, o);
    float inv = 1.f / s;
    out_attn[b * 64 + lane]      = e1 * inv;
    out_attn[b * 64 + lane + 32] = e2 * inv;
}

// ---------------------------------------------------------------------------
// k4: context[b,d] = sum_l attn[b,l] * features[b,l,d]
// ---------------------------------------------------------------------------
__global__ __launch_bounds__(256) void k4_context(
    const float* __restrict__ X, const float* __restrict__ attn,
    float* __restrict__ ctx)
{
    int b = blockIdx.x;
    __shared__ float as[64];
    if (threadIdx.x < 64) as[threadIdx.x] = attn[b * 64 + threadIdx.x];
    __syncthreads();

    const float4* Xb = (const float4*)(X + (size_t)b * NL * ND);
    int c = threadIdx.x;
    float4 acc = make_float4(0.f, 0.f, 0.f, 0.f);
    #pragma unroll 8
    for (int l = 0; l < NL; ++l) {
        float a = as[l];
        float4 f = Xb[(size_t)l * 256 + c];
        acc.x = fmaf(a, f.x, acc.x);
        acc.y = fmaf(a, f.y, acc.y);
        acc.z = fmaf(a, f.z, acc.z);
        acc.w = fmaf(a, f.w, acc.w);
    }
    ((float4*)(ctx + (size_t)b * ND))[c] = acc;
}

// ---------------------------------------------------------------------------
extern "C" void kernel_launch(void* const* d_in, const int* in_sizes, int n_in,
                              void* d_out, int out_size)
{
    const float* features = (const float*)d_in[0];
    const float* hidden   = (const float*)d_in[1];
    const float* W1_w     = (const float*)d_in[2];
    const float* W1_b     = (const float*)d_in[3];
    const float* W2_w     = (const float*)d_in[4];
    const float* W2_b     = (const float*)d_in[5];
    const float* V_w      = (const float*)d_in[6];
    // d_in[7] = V_b: unused (softmax shift-invariant)

    float* out  = (float*)d_out;
    float* ctx  = out;
    float* attn = out + (size_t)NB * ND;

    cudaFuncSetAttribute(k2_score_gemm,
                         cudaFuncAttributeMaxDynamicSharedMemorySize, SMEM_K2);

    kconvW<<<dim3(NU / 32, ND / 32), 256>>>(W1_w);
    kconvA<<<(NROWS * ND) / 4 / 256, 256>>>(features);
    k1_hidden_gemm<<<dim3(NB / 64, NU / 64), 256>>>(hidden, W2_w, W2_b);
    k2_score_gemm<<<dim3(NROWS / 128, NU / 128), 128, SMEM_K2>>>(W1_b, V_w);
    k3_softmax<<<NB / 8, 256>>>(attn);
    k4_context<<<NB, 256>>>(features, attn, ctx);
}

// round 7
// speedup vs baseline: 1.6019x; 1.0306x over previous
#include <cuda_runtime.h>
#include <cuda_fp16.h>
#include <math.h>
#include <stdint.h>

#define NB 512
#define NL 64
#define ND 1024
#define NU 512
#define NROWS (NB * NL)   // 32768 feature rows

// ---------------------------------------------------------------------------
// Device-global scratch (no allocation allowed)
// ---------------------------------------------------------------------------
__device__ __align__(1024) __half g_fa[(size_t)NROWS * ND];    // 64 MB, fp16 features
__device__ __align__(1024) __half g_W1Th[(size_t)NU * ND];     // [N=512][K=1024] hi
__device__ __align__(1024) __half g_W1Tl[(size_t)NU * ND];     // lo residual
__device__ float g_h[NB * NU];           // hidden @ W2 + b2
__device__ float g_lp[4 * NROWS];        // per-N-block partial logits

// ---------------------------------------------------------------------------
// PTX helpers (sm_80-era: valid on plain sm_103 target)
// ---------------------------------------------------------------------------
__device__ __forceinline__ uint32_t smem_u32(const void* p) {
    uint32_t a;
    asm("{ .reg .u64 t; cvta.to.shared.u64 t, %1; cvt.u32.u64 %0, t; }" : "=r"(a) : "l"(p));
    return a;
}
__device__ __forceinline__ void cp_async16(uint32_t dst, const void* src) {
    asm volatile("cp.async.cg.shared.global [%0], [%1], 16;" :: "r"(dst), "l"(src) : "memory");
}
__device__ __forceinline__ void cp_commit() {
    asm volatile("cp.async.commit_group;" ::: "memory");
}
template <int N> __device__ __forceinline__ void cp_wait() {
    asm volatile("cp.async.wait_group %0;" :: "n"(N) : "memory");
}
__device__ __forceinline__ void ldsm_x4(uint32_t* r, uint32_t addr) {
    asm volatile("ldmatrix.sync.aligned.m8n8.x4.shared.b16 {%0,%1,%2,%3}, [%4];"
                 : "=r"(r[0]), "=r"(r[1]), "=r"(r[2]), "=r"(r[3]) : "r"(addr));
}
__device__ __forceinline__ void mma_f16(float* c, const uint32_t* a, const uint32_t* b) {
    asm volatile(
        "mma.sync.aligned.m16n8k16.row.col.f32.f16.f16.f32 "
        "{%0,%1,%2,%3}, {%4,%5,%6,%7}, {%8,%9}, {%0,%1,%2,%3};"
        : "+f"(c[0]), "+f"(c[1]), "+f"(c[2]), "+f"(c[3])
        : "r"(a[0]), "r"(a[1]), "r"(a[2]), "r"(a[3]), "r"(b[0]), "r"(b[1]));
}

// fast tanh: 1 - 2/(exp2(2*log2e*x)+1); rel err ~1e-6. Saturates correctly.
__device__ __forceinline__ float tanh_fast(float x) {
    float e;
    asm("ex2.approx.f32 %0, %1;" : "=f"(e) : "f"(x * 2.88539008177792681f));
    float r;
    asm("rcp.approx.f32 %0, %1;" : "=f"(r) : "f"(e + 1.0f));
    return 1.0f - 2.0f * r;
}

// ---------------------------------------------------------------------------
// kconvA: features fp32 -> fp16 (single rounding). 4 elements per thread.
// ---------------------------------------------------------------------------
__global__ __launch_bounds__(256) void kconvA(const float* __restrict__ X)
{
    size_t i = ((size_t)blockIdx.x * 256 + threadIdx.x) * 4;
    float4 v = *(const float4*)(X + i);
    __half2 p0 = __floats2half2_rn(v.x, v.y);
    __half2 p1 = __floats2half2_rn(v.z, v.w);
    *(uint2*)((char*)g_fa + i * 2) =
        make_uint2(*(uint32_t*)&p0, *(uint32_t*)&p1);
}

// ---------------------------------------------------------------------------
// kconvW: W1 [K=1024, N=512] fp32 -> W1T hi/lo fp16 [N=512][K=1024]
// ---------------------------------------------------------------------------
__global__ __launch_bounds__(256) void kconvW(const float* __restrict__ W1)
{
    __shared__ float t[32][33];
    int n0 = blockIdx.x * 32, k0 = blockIdx.y * 32;
    int tx = threadIdx.x & 31, ty = threadIdx.x >> 5;   // 32 x 8
    #pragma unroll
    for (int i = 0; i < 32; i += 8)
        t[ty + i][tx] = W1[(size_t)(k0 + ty + i) * NU + n0 + tx];
    __syncthreads();
    #pragma unroll
    for (int i = 0; i < 32; i += 8) {
        float v = t[tx][ty + i];                 // = W1[k0+tx][n0+ty+i]
        __half h = __float2half_rn(v);
        size_t idx = (size_t)(n0 + ty + i) * ND + k0 + tx;
        g_W1Th[idx] = h;
        g_W1Tl[idx] = __float2half_rn(v - __half2float(h));
    }
}

// ---------------------------------------------------------------------------
// k1: h = hidden @ W2 + b2   (512x512x512, fp32 SIMT)
// ---------------------------------------------------------------------------
__global__ __launch_bounds__(256) void k1_hidden_gemm(
    const float* __restrict__ hidden, const float* __restrict__ W2,
    const float* __restrict__ b2)
{
    const int tid = threadIdx.x;
    const int tx = tid & 15, ty = tid >> 4;
    const int rowB = blockIdx.x * 64;
    const int nB   = blockIdx.y * 64;

    __shared__ float Xs[16][64];
    __shared__ float Ws[16][68];
    float acc[4][4] = {};

    for (int k0 = 0; k0 < NU; k0 += 16) {
        {
            int r = tid >> 2, c4 = (tid & 3) * 4;
            float4 v = *(const float4*)(hidden + (size_t)(rowB + r) * NU + k0 + c4);
            Xs[c4 + 0][r] = v.x; Xs[c4 + 1][r] = v.y;
            Xs[c4 + 2][r] = v.z; Xs[c4 + 3][r] = v.w;
        }
        {
            int k = tid >> 4, c4 = (tid & 15) * 4;
            *(float4*)&Ws[k][c4] = *(const float4*)(W2 + (size_t)(k0 + k) * NU + nB + c4);
        }
        __syncthreads();
        #pragma unroll
        for (int k = 0; k < 16; ++k) {
            float4 a = *(const float4*)&Xs[k][ty * 4];
            float4 b = *(const float4*)&Ws[k][tx * 4];
            float am[4] = {a.x, a.y, a.z, a.w};
            float bn[4] = {b.x, b.y, b.z, b.w};
            #pragma unroll
            for (int i = 0; i < 4; ++i)
                #pragma unroll
                for (int j = 0; j < 4; ++j)
                    acc[i][j] = fmaf(am[i], bn[j], acc[i][j]);
        }
        __syncthreads();
    }
    #pragma unroll
    for (int i = 0; i < 4; ++i)
        #pragma unroll
        for (int j = 0; j < 4; ++j)
            g_h[(size_t)(rowB + ty * 4 + i) * NU + nB + tx * 4 + j] =
                acc[i][j] + b2[nB + tx * 4 + j];
}

// ---------------------------------------------------------------------------
// k2: fp16 mma.sync GEMM, 2-term (A.Wh + A.Wl), fused epilogue.
// BM=128, BN=128, BK=32. 128 threads (4 warps: 2M x 2N, warp tile 64x64).
// 3-stage cp.async multistage with ONE barrier per chunk; loads issued
// immediately after the barrier so LDGSTS issue hides under the MMA phase.
// 2 CTAs/SM (smem ~92KB). 80B rows: ldmatrix conflict-free.
// ---------------------------------------------------------------------------
#define ROWB 80
#define TILE_B (128 * ROWB)      // 10240 bytes per tile
#define STG_B  (3 * TILE_B)      // A, Wh, Wl
#define STAGES 3
#define NCHUNK (ND / 32)
#define HS_OFF   (STAGES * STG_B)          // 2 x 128 floats
#define VS_OFF   (HS_OFF + 1024)           // 128 floats
#define PART_OFF (VS_OFF + 512)            // 128 x 2 floats
#define SMEM_K2  (PART_OFF + 1024)

__global__ __launch_bounds__(128, 2) void k2_score_gemm(
    const float* __restrict__ b1, const float* __restrict__ Vw)
{
    extern __shared__ __align__(1024) char smem[];
    const uint32_t sb = smem_u32(smem);
    const int tid  = threadIdx.x;
    const int lane = tid & 31, wid = tid >> 5;
    const int wm = wid >> 1, wn = wid & 1;     // 2 x 2 warp grid, 64x64 tiles
    const int rowB = blockIdx.x * 128;
    const int nB   = blockIdx.y * 128;

    float* hs   = (float*)(smem + HS_OFF);    // [2][128]
    float* Vs   = (float*)(smem + VS_OFF);    // [128]
    float* part = (float*)(smem + PART_OFF);  // [128][2]

    // epilogue constants (2 per thread)
    {
        int i0 = tid, i1 = tid + 128;
        hs[i0] = g_h[(size_t)(blockIdx.x * 2) * NU + nB + i0] + b1[nB + i0];
        hs[i1] = g_h[(size_t)(blockIdx.x * 2 + 1) * NU + nB + (i1 - 128)] + b1[nB + (i1 - 128)];
        Vs[tid] = Vw[nB + tid];
    }

    const __half* base0 = g_fa   + (size_t)rowB * ND;
    const __half* base1 = g_W1Th + (size_t)nB   * ND;
    const __half* base2 = g_W1Tl + (size_t)nB   * ND;

    // stage loader: 1536 x 16B chunks, 12 per thread
    auto load_stage = [&](int s, int kc) {
        uint32_t sdst = sb + s * STG_B;
        #pragma unroll
        for (int i = 0; i < 12; ++i) {
            int idx  = tid + i * 128;
            int tile = idx >> 9;               // 512 chunks per tile
            int rem  = idx & 511;
            int row  = rem >> 2, ch = rem & 3;
            const __half* gb = (tile == 0) ? base0 : (tile == 1) ? base1 : base2;
            cp_async16(sdst + tile * TILE_B + row * ROWB + ch * 16,
                       gb + (size_t)row * ND + kc * 32 + ch * 8);
        }
        cp_commit();
    };

    // prologue: fill 2 of the 3 stages (chunk c issues chunk c+2)
    load_stage(0, 0);
    load_stage(1, 1);

    float acc[4][8][4] = {};    // [mt 16-row][nt 8-col][vals]

    // precomputed ldmatrix intra-warp offsets
    const int a_row = ((lane >> 3) & 1) * 8 + (lane & 7);
    const int a_ch  = (lane >> 4);
    const int b_row = (lane >> 4) * 8 + (lane & 7);
    const int b_ch  = ((lane >> 3) & 1);

    for (int c = 0; c < NCHUNK; ++c) {
        int s = c % STAGES;
        cp_wait<1>();            // chunk c's stage has landed
        __syncthreads();         // all warps done reading stage (c-1)%3

        // issue next loads NOW (into the stage retired last chunk) so the
        // LDGSTS issue burst overlaps with this chunk's MMA phase
        if (c + 2 < NCHUNK) load_stage((c + 2) % STAGES, c + 2);
        else cp_commit();        // keep wait_group counts consistent

        uint32_t aB  = sb + s * STG_B;
        uint32_t whB = aB + TILE_B;
        uint32_t wlB = aB + 2 * TILE_B;

        #pragma unroll
        for (int kk = 0; kk < 2; ++kk) {
            uint32_t a[4][4], bh[8][2], bl[8][2];
            #pragma unroll
            for (int mt = 0; mt < 4; ++mt) {
                int r  = wm * 64 + mt * 16 + a_row;
                int ch = kk * 2 + a_ch;
                ldsm_x4(a[mt], aB + r * ROWB + ch * 16);
            }
            #pragma unroll
            for (int ntp = 0; ntp < 4; ++ntp) {
                int r  = wn * 64 + ntp * 16 + b_row;
                int ch = kk * 2 + b_ch;
                uint32_t t0[4], t1[4];
                ldsm_x4(t0, whB + r * ROWB + ch * 16);
                ldsm_x4(t1, wlB + r * ROWB + ch * 16);
                bh[ntp*2][0] = t0[0]; bh[ntp*2][1] = t0[1];
                bh[ntp*2+1][0] = t0[2]; bh[ntp*2+1][1] = t0[3];
                bl[ntp*2][0] = t1[0]; bl[ntp*2][1] = t1[1];
                bl[ntp*2+1][0] = t1[2]; bl[ntp*2+1][1] = t1[3];
            }
            #pragma unroll
            for (int mt = 0; mt < 4; ++mt)
                #pragma unroll
                for (int nt = 0; nt < 8; ++nt) {
                    mma_f16(acc[mt][nt], a[mt], bh[nt]);
                    mma_f16(acc[mt][nt], a[mt], bl[nt]);
                }
        }
    }

    // Fused epilogue: tanh(acc + b1 + h) . V  -> partial logits
    const int g = lane >> 2, tg4 = lane & 3;
    const int bloc = wm;               // warp tile 64 rows == one batch (L=64)
    #pragma unroll
    for (int mt = 0; mt < 4; ++mt) {
        float s0 = 0.f, s1 = 0.f;
        #pragma unroll
        for (int nt = 0; nt < 8; ++nt) {
            #pragma unroll
            for (int c2 = 0; c2 < 2; ++c2) {
                int col = wn * 64 + nt * 8 + tg4 * 2 + c2;
                float hb = hs[bloc * 128 + col];
                float vw = Vs[col];
                s0 = fmaf(tanh_fast(acc[mt][nt][c2]     + hb), vw, s0);
                s1 = fmaf(tanh_fast(acc[mt][nt][2 + c2] + hb), vw, s1);
            }
        }
        s0 += __shfl_xor_sync(0xFFFFFFFFu, s0, 1);
        s0 += __shfl_xor_sync(0xFFFFFFFFu, s0, 2);
        s1 += __shfl_xor_sync(0xFFFFFFFFu, s1, 1);
        s1 += __shfl_xor_sync(0xFFFFFFFFu, s1, 2);
        if (tg4 == 0) {
            int r0 = wm * 64 + mt * 16 + g;
            part[r0 * 2 + wn]       = s0;
            part[(r0 + 8) * 2 + wn] = s1;
        }
    }
    __syncthreads();
    g_lp[(size_t)blockIdx.y * NROWS + rowB + tid] = part[tid*2] + part[tid*2+1];
}

// ---------------------------------------------------------------------------
// k3: softmax over L=64 per batch (sums 4 N-block partials). Writes attn.
// ---------------------------------------------------------------------------
__global__ __launch_bounds__(256) void k3_softmax(float* __restrict__ out_attn)
{
    int b    = (blockIdx.x * 256 + threadIdx.x) >> 5;
    int lane = threadIdx.x & 31;

    float x1 = 0.f, x2 = 0.f;
    #pragma unroll
    for (int p = 0; p < 4; ++p) {
        x1 += g_lp[(size_t)p * NROWS + b * 64 + lane];
        x2 += g_lp[(size_t)p * NROWS + b * 64 + lane + 32];
    }
    float m = fmaxf(x1, x2);
    #pragma unroll
    for (int o = 16; o > 0; o >>= 1)
        m = fmaxf(m, __shfl_xor_sync(0xFFFFFFFFu, m, o));
    float e1 = expf(x1 - m), e2 = expf(x2 - m);
    float s = e1 + e2;
    #pragma unroll
    for (int o = 16; o > 0; o >>= 1)
        s += __shfl_xor_sync(0xFFFFFFFFu, s, o);
    float inv = 1.f / s;
    out_attn[b * 64 + lane]      = e1 * inv;
    out_attn[b * 64 + lane + 32] = e2 * inv;
}

// ---------------------------------------------------------------------------
// k4: context[b,d] = sum_l attn[b,l] * f16(features)[b,l,d]  (half traffic)
// ---------------------------------------------------------------------------
__global__ __launch_bounds__(256) void k4_context(
    const float* __restrict__ attn, float* __restrict__ ctx)
{
    int b = blockIdx.x;
    __shared__ float as[64];
    if (threadIdx.x < 64) as[threadIdx.x] = attn[b * 64 + threadIdx.x];
    __syncthreads();

    const __half* Xb = g_fa + (size_t)b * NL * ND;
    int c = threadIdx.x * 4;             // 4 halves per thread, 256 thr = 1024
    float4 acc = make_float4(0.f, 0.f, 0.f, 0.f);
    #pragma unroll 8
    for (int l = 0; l < NL; ++l) {
        float a = as[l];
        uint2 p = *(const uint2*)(Xb + (size_t)l * ND + c);
        float2 f0 = __half22float2(*(__half2*)&p.x);
        float2 f1 = __half22float2(*(__half2*)&p.y);
        acc.x = fmaf(a, f0.x, acc.x);
        acc.y = fmaf(a, f0.y, acc.y);
        acc.z = fmaf(a, f1.x, acc.z);
        acc.w = fmaf(a, f1.y, acc.w);
    }
    *(float4*)(ctx + (size_t)b * ND + c) = acc;
}

// ---------------------------------------------------------------------------
extern "C" void kernel_launch(void* const* d_in, const int* in_sizes, int n_in,
                              void* d_out, int out_size)
{
    const float* features = (const float*)d_in[0];
    const float* hidden   = (const float*)d_in[1];
    const float* W1_w     = (const float*)d_in[2];
    const float* W1_b     = (const float*)d_in[3];
    const float* W2_w     = (const float*)d_in[4];
    const float* W2_b     = (const float*)d_in[5];
    const float* V_w      = (const float*)d_in[6];
    // d_in[7] = V_b: unused (softmax shift-invariant)

    float* out  = (float*)d_out;
    float* ctx  = out;
    float* attn = out + (size_t)NB * ND;

    cudaFuncSetAttribute(k2_score_gemm,
                         cudaFuncAttributeMaxDynamicSharedMemorySize, SMEM_K2);

    kconvW<<<dim3(NU / 32, ND / 32), 256>>>(W1_w);
    kconvA<<<(NROWS * ND) / 4 / 256, 256>>>(features);
    k1_hidden_gemm<<<dim3(NB / 64, NU / 64), 256>>>(hidden, W2_w, W2_b);
    k2_score_gemm<<<dim3(NROWS / 128, NU / 128), 128, SMEM_K2>>>(W1_b, V_w);
    k3_softmax<<<NB / 8, 256>>>(attn);
    k4_context<<<NB, 256>>>(attn, ctx);
}

// round 8
// speedup vs baseline: 2.3110x; 1.4426x over previous
#include <cuda_runtime.h>
#include <cuda_fp16.h>
#include <math.h>
#include <stdint.h>

#define NB 512
#define NL 64
#define ND 1024
#define NU 512
#define NROWS (NB * NL)   // 32768 feature rows

// ---------------------------------------------------------------------------
// Device-global scratch (no allocation allowed)
// ---------------------------------------------------------------------------
__device__ __align__(1024) __half g_fa[(size_t)NROWS * ND];    // 64 MB, fp16 features
__device__ __align__(1024) __half g_W1Th[(size_t)NU * ND];     // [N=512][K=1024] fp16
__device__ float g_h[NB * NU];           // hidden @ W2 + b2
__device__ float g_lp[4 * NROWS];        // per-N-block partial logits

// ---------------------------------------------------------------------------
// PTX helpers (sm_80-era: valid on plain sm_103 target)
// ---------------------------------------------------------------------------
__device__ __forceinline__ uint32_t smem_u32(const void* p) {
    uint32_t a;
    asm("{ .reg .u64 t; cvta.to.shared.u64 t, %1; cvt.u32.u64 %0, t; }" : "=r"(a) : "l"(p));
    return a;
}
__device__ __forceinline__ void cp_async16(uint32_t dst, const void* src) {
    asm volatile("cp.async.cg.shared.global [%0], [%1], 16;" :: "r"(dst), "l"(src) : "memory");
}
__device__ __forceinline__ void cp_commit() {
    asm volatile("cp.async.commit_group;" ::: "memory");
}
template <int N> __device__ __forceinline__ void cp_wait() {
    asm volatile("cp.async.wait_group %0;" :: "n"(N) : "memory");
}
__device__ __forceinline__ void ldsm_x4(uint32_t* r, uint32_t addr) {
    asm volatile("ldmatrix.sync.aligned.m8n8.x4.shared.b16 {%0,%1,%2,%3}, [%4];"
                 : "=r"(r[0]), "=r"(r[1]), "=r"(r[2]), "=r"(r[3]) : "r"(addr));
}
__device__ __forceinline__ void mma_f16(float* c, const uint32_t* a, const uint32_t* b) {
    asm volatile(
        "mma.sync.aligned.m16n8k16.row.col.f32.f16.f16.f32 "
        "{%0,%1,%2,%3}, {%4,%5,%6,%7}, {%8,%9}, {%0,%1,%2,%3};"
        : "+f"(c[0]), "+f"(c[1]), "+f"(c[2]), "+f"(c[3])
        : "r"(a[0]), "r"(a[1]), "r"(a[2]), "r"(a[3]), "r"(b[0]), "r"(b[1]));
}

// fast tanh: 1 - 2/(exp2(2*log2e*x)+1); rel err ~1e-6. Saturates correctly.
__device__ __forceinline__ float tanh_fast(float x) {
    float e;
    asm("ex2.approx.f32 %0, %1;" : "=f"(e) : "f"(x * 2.88539008177792681f));
    float r;
    asm("rcp.approx.f32 %0, %1;" : "=f"(r) : "f"(e + 1.0f));
    return 1.0f - 2.0f * r;
}

// ---------------------------------------------------------------------------
// kconvA: features fp32 -> fp16 (single rounding). 4 elements per thread.
// ---------------------------------------------------------------------------
__global__ __launch_bounds__(256) void kconvA(const float* __restrict__ X)
{
    size_t i = ((size_t)blockIdx.x * 256 + threadIdx.x) * 4;
    float4 v = *(const float4*)(X + i);
    __half2 p0 = __floats2half2_rn(v.x, v.y);
    __half2 p1 = __floats2half2_rn(v.z, v.w);
    *(uint2*)((char*)g_fa + i * 2) =
        make_uint2(*(uint32_t*)&p0, *(uint32_t*)&p1);
}

// ---------------------------------------------------------------------------
// kconvW: W1 [K=1024, N=512] fp32 -> W1T fp16 [N=512][K=1024] (transpose)
// ---------------------------------------------------------------------------
__global__ __launch_bounds__(256) void kconvW(const float* __restrict__ W1)
{
    __shared__ float t[32][33];
    int n0 = blockIdx.x * 32, k0 = blockIdx.y * 32;
    int tx = threadIdx.x & 31, ty = threadIdx.x >> 5;   // 32 x 8
    #pragma unroll
    for (int i = 0; i < 32; i += 8)
        t[ty + i][tx] = W1[(size_t)(k0 + ty + i) * NU + n0 + tx];
    __syncthreads();
    #pragma unroll
    for (int i = 0; i < 32; i += 8) {
        float v = t[tx][ty + i];                 // = W1[k0+tx][n0+ty+i]
        g_W1Th[(size_t)(n0 + ty + i) * ND + k0 + tx] = __float2half_rn(v);
    }
}

// ---------------------------------------------------------------------------
// k1: h = hidden @ W2 + b2   (512x512x512, fp32 SIMT)
// ---------------------------------------------------------------------------
__global__ __launch_bounds__(256) void k1_hidden_gemm(
    const float* __restrict__ hidden, const float* __restrict__ W2,
    const float* __restrict__ b2)
{
    const int tid = threadIdx.x;
    const int tx = tid & 15, ty = tid >> 4;
    const int rowB = blockIdx.x * 64;
    const int nB   = blockIdx.y * 64;

    __shared__ float Xs[16][64];
    __shared__ float Ws[16][68];
    float acc[4][4] = {};

    for (int k0 = 0; k0 < NU; k0 += 16) {
        {
            int r = tid >> 2, c4 = (tid & 3) * 4;
            float4 v = *(const float4*)(hidden + (size_t)(rowB + r) * NU + k0 + c4);
            Xs[c4 + 0][r] = v.x; Xs[c4 + 1][r] = v.y;
            Xs[c4 + 2][r] = v.z; Xs[c4 + 3][r] = v.w;
        }
        {
            int k = tid >> 4, c4 = (tid & 15) * 4;
            *(float4*)&Ws[k][c4] = *(const float4*)(W2 + (size_t)(k0 + k) * NU + nB + c4);
        }
        __syncthreads();
        #pragma unroll
        for (int k = 0; k < 16; ++k) {
            float4 a = *(const float4*)&Xs[k][ty * 4];
            float4 b = *(const float4*)&Ws[k][tx * 4];
            float am[4] = {a.x, a.y, a.z, a.w};
            float bn[4] = {b.x, b.y, b.z, b.w};
            #pragma unroll
            for (int i = 0; i < 4; ++i)
                #pragma unroll
                for (int j = 0; j < 4; ++j)
                    acc[i][j] = fmaf(am[i], bn[j], acc[i][j]);
        }
        __syncthreads();
    }
    #pragma unroll
    for (int i = 0; i < 4; ++i)
        #pragma unroll
        for (int j = 0; j < 4; ++j)
            g_h[(size_t)(rowB + ty * 4 + i) * NU + nB + tx * 4 + j] =
                acc[i][j] + b2[nB + tx * 4 + j];
}

// ---------------------------------------------------------------------------
// k2: fp16 mma.sync GEMM, single term (A.Wh), fused epilogue.
// BM=128, BN=128, BK=32. 128 threads (4 warps: 2M x 2N, warp tile 64x64).
// 4-stage cp.async multistage, one barrier per chunk; loads issued right
// after the barrier so LDGSTS issue hides under the MMA phase.
// 2 CTAs/SM (smem ~84KB). 80B rows: ldmatrix conflict-free.
// ---------------------------------------------------------------------------
#define ROWB 80
#define TILE_B (128 * ROWB)      // 10240 bytes per tile
#define STG_B  (2 * TILE_B)      // A, Wh
#define STAGES 4
#define NCHUNK (ND / 32)
#define HS_OFF   (STAGES * STG_B)          // 2 x 128 floats
#define VS_OFF   (HS_OFF + 1024)           // 128 floats
#define PART_OFF (VS_OFF + 512)            // 128 x 2 floats
#define SMEM_K2  (PART_OFF + 1024)

__global__ __launch_bounds__(128, 2) void k2_score_gemm(
    const float* __restrict__ b1, const float* __restrict__ Vw)
{
    extern __shared__ __align__(1024) char smem[];
    const uint32_t sb = smem_u32(smem);
    const int tid  = threadIdx.x;
    const int lane = tid & 31, wid = tid >> 5;
    const int wm = wid >> 1, wn = wid & 1;     // 2 x 2 warp grid, 64x64 tiles
    const int rowB = blockIdx.x * 128;
    const int nB   = blockIdx.y * 128;

    float* hs   = (float*)(smem + HS_OFF);    // [2][128]
    float* Vs   = (float*)(smem + VS_OFF);    // [128]
    float* part = (float*)(smem + PART_OFF);  // [128][2]

    // epilogue constants (2 per thread)
    {
        int i0 = tid, i1 = tid + 128;
        hs[i0] = g_h[(size_t)(blockIdx.x * 2) * NU + nB + i0] + b1[nB + i0];
        hs[i1] = g_h[(size_t)(blockIdx.x * 2 + 1) * NU + nB + (i1 - 128)] + b1[nB + (i1 - 128)];
        Vs[tid] = Vw[nB + tid];
    }

    const __half* base0 = g_fa   + (size_t)rowB * ND;
    const __half* base1 = g_W1Th + (size_t)nB   * ND;

    // stage loader: 1024 x 16B chunks, 8 per thread
    auto load_stage = [&](int s, int kc) {
        uint32_t sdst = sb + s * STG_B;
        #pragma unroll
        for (int i = 0; i < 8; ++i) {
            int idx  = tid + i * 128;
            int tile = idx >> 9;               // 512 chunks per tile
            int rem  = idx & 511;
            int row  = rem >> 2, ch = rem & 3;
            const __half* gb = (tile == 0) ? base0 : base1;
            cp_async16(sdst + tile * TILE_B + row * ROWB + ch * 16,
                       gb + (size_t)row * ND + kc * 32 + ch * 8);
        }
        cp_commit();
    };

    // prologue: fill 3 of the 4 stages (chunk c issues chunk c+3)
    load_stage(0, 0);
    load_stage(1, 1);
    load_stage(2, 2);

    float acc[4][8][4] = {};    // [mt 16-row][nt 8-col][vals]

    // precomputed ldmatrix intra-warp offsets
    const int a_row = ((lane >> 3) & 1) * 8 + (lane & 7);
    const int a_ch  = (lane >> 4);
    const int b_row = (lane >> 4) * 8 + (lane & 7);
    const int b_ch  = ((lane >> 3) & 1);

    for (int c = 0; c < NCHUNK; ++c) {
        int s = c % STAGES;
        cp_wait<STAGES - 2>();   // chunk c's stage has landed
        __syncthreads();         // all warps done reading stage (c-1)%4

        // issue next loads NOW (into the stage retired last chunk) so the
        // LDGSTS issue burst overlaps with this chunk's MMA phase
        if (c + 3 < NCHUNK) load_stage((c + 3) % STAGES, c + 3);
        else cp_commit();        // keep wait_group counts consistent

        uint32_t aB  = sb + s * STG_B;
        uint32_t whB = aB + TILE_B;

        #pragma unroll
        for (int kk = 0; kk < 2; ++kk) {
            uint32_t a[4][4], bh[8][2];
            #pragma unroll
            for (int mt = 0; mt < 4; ++mt) {
                int r  = wm * 64 + mt * 16 + a_row;
                int ch = kk * 2 + a_ch;
                ldsm_x4(a[mt], aB + r * ROWB + ch * 16);
            }
            #pragma unroll
            for (int ntp = 0; ntp < 4; ++ntp) {
                int r  = wn * 64 + ntp * 16 + b_row;
                int ch = kk * 2 + b_ch;
                uint32_t t0[4];
                ldsm_x4(t0, whB + r * ROWB + ch * 16);
                bh[ntp*2][0] = t0[0]; bh[ntp*2][1] = t0[1];
                bh[ntp*2+1][0] = t0[2]; bh[ntp*2+1][1] = t0[3];
            }
            #pragma unroll
            for (int mt = 0; mt < 4; ++mt)
                #pragma unroll
                for (int nt = 0; nt < 8; ++nt)
                    mma_f16(acc[mt][nt], a[mt], bh[nt]);
        }
    }

    // Fused epilogue: tanh(acc + b1 + h) . V  -> partial logits
    const int g = lane >> 2, tg4 = lane & 3;
    const int bloc = wm;               // warp tile 64 rows == one batch (L=64)
    #pragma unroll
    for (int mt = 0; mt < 4; ++mt) {
        float s0 = 0.f, s1 = 0.f;
        #pragma unroll
        for (int nt = 0; nt < 8; ++nt) {
            #pragma unroll
            for (int c2 = 0; c2 < 2; ++c2) {
                int col = wn * 64 + nt * 8 + tg4 * 2 + c2;
                float hb = hs[bloc * 128 + col];
                float vw = Vs[col];
                s0 = fmaf(tanh_fast(acc[mt][nt][c2]     + hb), vw, s0);
                s1 = fmaf(tanh_fast(acc[mt][nt][2 + c2] + hb), vw, s1);
            }
        }
        s0 += __shfl_xor_sync(0xFFFFFFFFu, s0, 1);
        s0 += __shfl_xor_sync(0xFFFFFFFFu, s0, 2);
        s1 += __shfl_xor_sync(0xFFFFFFFFu, s1, 1);
        s1 += __shfl_xor_sync(0xFFFFFFFFu, s1, 2);
        if (tg4 == 0) {
            int r0 = wm * 64 + mt * 16 + g;
            part[r0 * 2 + wn]       = s0;
            part[(r0 + 8) * 2 + wn] = s1;
        }
    }
    __syncthreads();
    g_lp[(size_t)blockIdx.y * NROWS + rowB + tid] = part[tid*2] + part[tid*2+1];
}

// ---------------------------------------------------------------------------
// k3: softmax over L=64 per batch (sums 4 N-block partials). Writes attn.
// ---------------------------------------------------------------------------
__global__ __launch_bounds__(256) void k3_softmax(float* __restrict__ out_attn)
{
    int b    = (blockIdx.x * 256 + threadIdx.x) >> 5;
    int lane = threadIdx.x & 31;

    float x1 = 0.f, x2 = 0.f;
    #pragma unroll
    for (int p = 0; p < 4; ++p) {
        x1 += g_lp[(size_t)p * NROWS + b * 64 + lane];
        x2 += g_lp[(size_t)p * NROWS + b * 64 + lane + 32];
    }
    float m = fmaxf(x1, x2);
    #pragma unroll
    for (int o = 16; o > 0; o >>= 1)
        m = fmaxf(m, __shfl_xor_sync(0xFFFFFFFFu, m, o));
    float e1 = expf(x1 - m), e2 = expf(x2 - m);
    float s = e1 + e2;
    #pragma unroll
    for (int o = 16; o > 0; o >>= 1)
        s += __shfl_xor_sync(0xFFFFFFFFu, s, o);
    float inv = 1.f / s;
    out_attn[b * 64 + lane]      = e1 * inv;
    out_attn[b * 64 + lane + 32] = e2 * inv;
}

// ---------------------------------------------------------------------------
// k4: context[b,d] = sum_l attn[b,l] * f16(features)[b,l,d]  (half traffic)
// ---------------------------------------------------------------------------
__global__ __launch_bounds__(256) void k4_context(
    const float* __restrict__ attn, float* __restrict__ ctx)
{
    int b = blockIdx.x;
    __shared__ float as[64];
    if (threadIdx.x < 64) as[threadIdx.x] = attn[b * 64 + threadIdx.x];
    __syncthreads();

    const __half* Xb = g_fa + (size_t)b * NL * ND;
    int c = threadIdx.x * 4;             // 4 halves per thread, 256 thr = 1024
    float4 acc = make_float4(0.f, 0.f, 0.f, 0.f);
    #pragma unroll 8
    for (int l = 0; l < NL; ++l) {
        float a = as[l];
        uint2 p = *(const uint2*)(Xb + (size_t)l * ND + c);
        float2 f0 = __half22float2(*(__half2*)&p.x);
        float2 f1 = __half22float2(*(__half2*)&p.y);
        acc.x = fmaf(a, f0.x, acc.x);
        acc.y = fmaf(a, f0.y, acc.y);
        acc.z = fmaf(a, f1.x, acc.z);
        acc.w = fmaf(a, f1.y, acc.w);
    }
    *(float4*)(ctx + (size_t)b * ND + c) = acc;
}

// ---------------------------------------------------------------------------
extern "C" void kernel_launch(void* const* d_in, const int* in_sizes, int n_in,
                              void* d_out, int out_size)
{
    const float* features = (const float*)d_in[0];
    const float* hidden   = (const float*)d_in[1];
    const float* W1_w     = (const float*)d_in[2];
    const float* W1_b     = (const float*)d_in[3];
    const float* W2_w     = (const float*)d_in[4];
    const float* W2_b     = (const float*)d_in[5];
    const float* V_w      = (const float*)d_in[6];
    // d_in[7] = V_b: unused (softmax shift-invariant)

    float* out  = (float*)d_out;
    float* ctx  = out;
    float* attn = out + (size_t)NB * ND;

    cudaFuncSetAttribute(k2_score_gemm,
                         cudaFuncAttributeMaxDynamicSharedMemorySize, SMEM_K2);

    kconvW<<<dim3(NU / 32, ND / 32), 256>>>(W1_w);
    kconvA<<<(NROWS * ND) / 4 / 256, 256>>>(features);
    k1_hidden_gemm<<<dim3(NB / 64, NU / 64), 256>>>(hidden, W2_w, W2_b);
    k2_score_gemm<<<dim3(NROWS / 128, NU / 128), 128, SMEM_K2>>>(W1_b, V_w);
    k3_softmax<<<NB / 8, 256>>>(attn);
    k4_context<<<NB, 256>>>(attn, ctx);
}

// round 9
// speedup vs baseline: 2.6886x; 1.1634x over previous
#include <cuda_runtime.h>
#include <cuda_fp16.h>
#include <math.h>
#include <stdint.h>

#define NB 512
#define NL 64
#define ND 1024
#define NU 512
#define NROWS (NB * NL)   // 32768 feature rows

// ---------------------------------------------------------------------------
// Device-global scratch (no allocation allowed)
// ---------------------------------------------------------------------------
__device__ __align__(1024) __half g_fa[(size_t)NROWS * ND];    // 64 MB, fp16 features
__device__ __align__(1024) __half g_W1Th[(size_t)NU * ND];     // [N=512][K=1024] fp16
__device__ float g_h[NB * NU];           // hidden @ W2 + b2
__device__ float g_lp[4 * NROWS];        // per-N-block partial logits

// ---------------------------------------------------------------------------
// PTX helpers (sm_80-era: valid on plain sm_103 target)
// ---------------------------------------------------------------------------
__device__ __forceinline__ uint32_t smem_u32(const void* p) {
    uint32_t a;
    asm("{ .reg .u64 t; cvta.to.shared.u64 t, %1; cvt.u32.u64 %0, t; }" : "=r"(a) : "l"(p));
    return a;
}
__device__ __forceinline__ void cp_async16(uint32_t dst, const void* src) {
    asm volatile("cp.async.cg.shared.global [%0], [%1], 16;" :: "r"(dst), "l"(src) : "memory");
}
__device__ __forceinline__ void cp_commit() {
    asm volatile("cp.async.commit_group;" ::: "memory");
}
template <int N> __device__ __forceinline__ void cp_wait() {
    asm volatile("cp.async.wait_group %0;" :: "n"(N) : "memory");
}
__device__ __forceinline__ void ldsm_x4(uint32_t* r, uint32_t addr) {
    asm volatile("ldmatrix.sync.aligned.m8n8.x4.shared.b16 {%0,%1,%2,%3}, [%4];"
                 : "=r"(r[0]), "=r"(r[1]), "=r"(r[2]), "=r"(r[3]) : "r"(addr));
}
__device__ __forceinline__ void mma_f16(float* c, const uint32_t* a, const uint32_t* b) {
    asm volatile(
        "mma.sync.aligned.m16n8k16.row.col.f32.f16.f16.f32 "
        "{%0,%1,%2,%3}, {%4,%5,%6,%7}, {%8,%9}, {%0,%1,%2,%3};"
        : "+f"(c[0]), "+f"(c[1]), "+f"(c[2]), "+f"(c[3])
        : "r"(a[0]), "r"(a[1]), "r"(a[2]), "r"(a[3]), "r"(b[0]), "r"(b[1]));
}

// fast tanh: 1 - 2/(exp2(2*log2e*x)+1); rel err ~1e-6. Saturates correctly.
__device__ __forceinline__ float tanh_fast(float x) {
    float e;
    asm("ex2.approx.f32 %0, %1;" : "=f"(e) : "f"(x * 2.88539008177792681f));
    float r;
    asm("rcp.approx.f32 %0, %1;" : "=f"(r) : "f"(e + 1.0f));
    return 1.0f - 2.0f * r;
}

// ---------------------------------------------------------------------------
// kprep: fused prepass. One launch, three block roles (scheduled in order):
//   blocks [0,64)        : k1  h = hidden @ W2 + b2  (64x64 tiles)
//   blocks [64,576)      : kconvW  W1 -> W1T fp16 transpose
//   blocks [576,33344)   : kconvA  features fp32 -> fp16
// k1/kconvW blocks land in wave 1 and hide under the memory-bound kconvA.
// ---------------------------------------------------------------------------
#define PREP_K1   64
#define PREP_KW   512
#define PREP_GRID (PREP_K1 + PREP_KW + 32768)

__global__ __launch_bounds__(256) void kprep(
    const float* __restrict__ features, const float* __restrict__ hidden,
    const float* __restrict__ W1,       const float* __restrict__ W2,
    const float* __restrict__ b2)
{
    __shared__ __align__(16) char sm[8704];
    const int bid = blockIdx.x;
    const int tid = threadIdx.x;

    if (bid >= PREP_K1 + PREP_KW) {
        // ---- kconvA: fp32 -> fp16, 4 elements per thread ----
        size_t i = ((size_t)(bid - PREP_K1 - PREP_KW) * 256 + tid) * 4;
        float4 v = *(const float4*)(features + i);
        __half2 p0 = __floats2half2_rn(v.x, v.y);
        __half2 p1 = __floats2half2_rn(v.z, v.w);
        *(uint2*)((char*)g_fa + i * 2) =
            make_uint2(*(uint32_t*)&p0, *(uint32_t*)&p1);
        return;
    }

    if (bid >= PREP_K1) {
        // ---- kconvW: W1 [K,N] fp32 -> W1T [N,K] fp16 (32x32 tiles) ----
        float (*t)[33] = (float (*)[33])sm;
        int b  = bid - PREP_K1;
        int n0 = (b & 15) * 32, k0 = (b >> 4) * 32;
        int tx = tid & 31, ty = tid >> 5;   // 32 x 8
        #pragma unroll
        for (int i = 0; i < 32; i += 8)
            t[ty + i][tx] = W1[(size_t)(k0 + ty + i) * NU + n0 + tx];
        __syncthreads();
        #pragma unroll
        for (int i = 0; i < 32; i += 8) {
            float v = t[tx][ty + i];                 // = W1[k0+tx][n0+ty+i]
            g_W1Th[(size_t)(n0 + ty + i) * ND + k0 + tx] = __float2half_rn(v);
        }
        return;
    }

    // ---- k1: h = hidden @ W2 + b2 (512x512x512 fp32, 64x64 tiles) ----
    {
        float (*Xs)[64] = (float (*)[64])sm;                 // 16x64
        float (*Ws)[68] = (float (*)[68])(sm + 4096);        // 16x68
        const int tx = tid & 15, ty = tid >> 4;
        const int rowB = (bid & 7) * 64;
        const int nB   = (bid >> 3) * 64;
        float acc[4][4] = {};

        for (int k0 = 0; k0 < NU; k0 += 16) {
            {
                int r = tid >> 2, c4 = (tid & 3) * 4;
                float4 v = *(const float4*)(hidden + (size_t)(rowB + r) * NU + k0 + c4);
                Xs[c4 + 0][r] = v.x; Xs[c4 + 1][r] = v.y;
                Xs[c4 + 2][r] = v.z; Xs[c4 + 3][r] = v.w;
            }
            {
                int k = tid >> 4, c4 = (tid & 15) * 4;
                *(float4*)&Ws[k][c4] = *(const float4*)(W2 + (size_t)(k0 + k) * NU + nB + c4);
            }
            __syncthreads();
            #pragma unroll
            for (int k = 0; k < 16; ++k) {
                float4 a = *(const float4*)&Xs[k][ty * 4];
                float4 b = *(const float4*)&Ws[k][tx * 4];
                float am[4] = {a.x, a.y, a.z, a.w};
                float bn[4] = {b.x, b.y, b.z, b.w};
                #pragma unroll
                for (int i = 0; i < 4; ++i)
                    #pragma unroll
                    for (int j = 0; j < 4; ++j)
                        acc[i][j] = fmaf(am[i], bn[j], acc[i][j]);
            }
            __syncthreads();
        }
        #pragma unroll
        for (int i = 0; i < 4; ++i)
            #pragma unroll
            for (int j = 0; j < 4; ++j)
                g_h[(size_t)(rowB + ty * 4 + i) * NU + nB + tx * 4 + j] =
                    acc[i][j] + b2[nB + tx * 4 + j];
    }
}

// ---------------------------------------------------------------------------
// k2: fp16 mma.sync GEMM, single term (A.Wh), fused epilogue.
// BM=128, BN=128, BK=32. 128 threads (4 warps: 2M x 2N, warp tile 64x64).
// 5-stage cp.async multistage, one barrier per chunk; loads issued right
// after the barrier so LDGSTS issue hides under the MMA phase.
// 2 CTAs/SM (smem ~102KB). 80B rows: ldmatrix conflict-free.
// ---------------------------------------------------------------------------
#define ROWB 80
#define TILE_B (128 * ROWB)      // 10240 bytes per tile
#define STG_B  (2 * TILE_B)      // A, Wh
#define STAGES 5
#define NCHUNK (ND / 32)
#define HS_OFF   (STAGES * STG_B)          // 2 x 128 floats
#define VS_OFF   (HS_OFF + 1024)           // 128 floats
#define PART_OFF (VS_OFF + 512)            // 128 x 2 floats
#define SMEM_K2  (PART_OFF + 1024)

__global__ __launch_bounds__(128, 2) void k2_score_gemm(
    const float* __restrict__ b1, const float* __restrict__ Vw)
{
    extern __shared__ __align__(1024) char smem[];
    const uint32_t sb = smem_u32(smem);
    const int tid  = threadIdx.x;
    const int lane = tid & 31, wid = tid >> 5;
    const int wm = wid >> 1, wn = wid & 1;     // 2 x 2 warp grid, 64x64 tiles
    const int rowB = blockIdx.x * 128;
    const int nB   = blockIdx.y * 128;

    float* hs   = (float*)(smem + HS_OFF);    // [2][128]
    float* Vs   = (float*)(smem + VS_OFF);    // [128]
    float* part = (float*)(smem + PART_OFF);  // [128][2]

    // epilogue constants (2 per thread)
    {
        int i0 = tid, i1 = tid + 128;
        hs[i0] = g_h[(size_t)(blockIdx.x * 2) * NU + nB + i0] + b1[nB + i0];
        hs[i1] = g_h[(size_t)(blockIdx.x * 2 + 1) * NU + nB + (i1 - 128)] + b1[nB + (i1 - 128)];
        Vs[tid] = Vw[nB + tid];
    }

    const __half* base0 = g_fa   + (size_t)rowB * ND;
    const __half* base1 = g_W1Th + (size_t)nB   * ND;

    // stage loader: 1024 x 16B chunks, 8 per thread
    auto load_stage = [&](int s, int kc) {
        uint32_t sdst = sb + s * STG_B;
        #pragma unroll
        for (int i = 0; i < 8; ++i) {
            int idx  = tid + i * 128;
            int tile = idx >> 9;               // 512 chunks per tile
            int rem  = idx & 511;
            int row  = rem >> 2, ch = rem & 3;
            const __half* gb = (tile == 0) ? base0 : base1;
            cp_async16(sdst + tile * TILE_B + row * ROWB + ch * 16,
                       gb + (size_t)row * ND + kc * 32 + ch * 8);
        }
        cp_commit();
    };

    // prologue: fill 4 of the 5 stages (chunk c issues chunk c+4)
    load_stage(0, 0);
    load_stage(1, 1);
    load_stage(2, 2);
    load_stage(3, 3);

    float acc[4][8][4] = {};    // [mt 16-row][nt 8-col][vals]

    // precomputed ldmatrix intra-warp offsets
    const int a_row = ((lane >> 3) & 1) * 8 + (lane & 7);
    const int a_ch  = (lane >> 4);
    const int b_row = (lane >> 4) * 8 + (lane & 7);
    const int b_ch  = ((lane >> 3) & 1);

    for (int c = 0; c < NCHUNK; ++c) {
        int s = c % STAGES;
        cp_wait<STAGES - 2>();   // chunk c's stage has landed
        __syncthreads();         // all warps done reading stage (c-1)%5

        // issue next loads NOW (into the stage retired last chunk) so the
        // LDGSTS issue burst overlaps with this chunk's MMA phase
        if (c + 4 < NCHUNK) load_stage((c + 4) % STAGES, c + 4);
        else cp_commit();        // keep wait_group counts consistent

        uint32_t aB  = sb + s * STG_B;
        uint32_t whB = aB + TILE_B;

        #pragma unroll
        for (int kk = 0; kk < 2; ++kk) {
            uint32_t a[4][4], bh[8][2];
            #pragma unroll
            for (int mt = 0; mt < 4; ++mt) {
                int r  = wm * 64 + mt * 16 + a_row;
                int ch = kk * 2 + a_ch;
                ldsm_x4(a[mt], aB + r * ROWB + ch * 16);
            }
            #pragma unroll
            for (int ntp = 0; ntp < 4; ++ntp) {
                int r  = wn * 64 + ntp * 16 + b_row;
                int ch = kk * 2 + b_ch;
                uint32_t t0[4];
                ldsm_x4(t0, whB + r * ROWB + ch * 16);
                bh[ntp*2][0] = t0[0]; bh[ntp*2][1] = t0[1];
                bh[ntp*2+1][0] = t0[2]; bh[ntp*2+1][1] = t0[3];
            }
            #pragma unroll
            for (int mt = 0; mt < 4; ++mt)
                #pragma unroll
                for (int nt = 0; nt < 8; ++nt)
                    mma_f16(acc[mt][nt], a[mt], bh[nt]);
        }
    }

    // Fused epilogue: tanh(acc + b1 + h) . V  -> partial logits
    const int g = lane >> 2, tg4 = lane & 3;
    const int bloc = wm;               // warp tile 64 rows == one batch (L=64)
    #pragma unroll
    for (int mt = 0; mt < 4; ++mt) {
        float s0 = 0.f, s1 = 0.f;
        #pragma unroll
        for (int nt = 0; nt < 8; ++nt) {
            #pragma unroll
            for (int c2 = 0; c2 < 2; ++c2) {
                int col = wn * 64 + nt * 8 + tg4 * 2 + c2;
                float hb = hs[bloc * 128 + col];
                float vw = Vs[col];
                s0 = fmaf(tanh_fast(acc[mt][nt][c2]     + hb), vw, s0);
                s1 = fmaf(tanh_fast(acc[mt][nt][2 + c2] + hb), vw, s1);
            }
        }
        s0 += __shfl_xor_sync(0xFFFFFFFFu, s0, 1);
        s0 += __shfl_xor_sync(0xFFFFFFFFu, s0, 2);
        s1 += __shfl_xor_sync(0xFFFFFFFFu, s1, 1);
        s1 += __shfl_xor_sync(0xFFFFFFFFu, s1, 2);
        if (tg4 == 0) {
            int r0 = wm * 64 + mt * 16 + g;
            part[r0 * 2 + wn]       = s0;
            part[(r0 + 8) * 2 + wn] = s1;
        }
    }
    __syncthreads();
    g_lp[(size_t)blockIdx.y * NROWS + rowB + tid] = part[tid*2] + part[tid*2+1];
}

// ---------------------------------------------------------------------------
// k3: softmax over L=64 per batch (sums 4 N-block partials). Writes attn.
// ---------------------------------------------------------------------------
__global__ __launch_bounds__(256) void k3_softmax(float* __restrict__ out_attn)
{
    int b    = (blockIdx.x * 256 + threadIdx.x) >> 5;
    int lane = threadIdx.x & 31;

    float x1 = 0.f, x2 = 0.f;
    #pragma unroll
    for (int p = 0; p < 4; ++p) {
        x1 += g_lp[(size_t)p * NROWS + b * 64 + lane];
        x2 += g_lp[(size_t)p * NROWS + b * 64 + lane + 32];
    }
    float m = fmaxf(x1, x2);
    #pragma unroll
    for (int o = 16; o > 0; o >>= 1)
        m = fmaxf(m, __shfl_xor_sync(0xFFFFFFFFu, m, o));
    float e1 = expf(x1 - m), e2 = expf(x2 - m);
    float s = e1 + e2;
    #pragma unroll
    for (int o = 16; o > 0; o >>= 1)
        s += __shfl_xor_sync(0xFFFFFFFFu, s, o);
    float inv = 1.f / s;
    out_attn[b * 64 + lane]      = e1 * inv;
    out_attn[b * 64 + lane + 32] = e2 * inv;
}

// ---------------------------------------------------------------------------
// k4: context[b,d] = sum_l attn[b,l] * f16(features)[b,l,d]  (half traffic)
// ---------------------------------------------------------------------------
__global__ __launch_bounds__(256) void k4_context(
    const float* __restrict__ attn, float* __restrict__ ctx)
{
    int b = blockIdx.x;
    __shared__ float as[64];
    if (threadIdx.x < 64) as[threadIdx.x] = attn[b * 64 + threadIdx.x];
    __syncthreads();

    const __half* Xb = g_fa + (size_t)b * NL * ND;
    int c = threadIdx.x * 4;             // 4 halves per thread, 256 thr = 1024
    float4 acc = make_float4(0.f, 0.f, 0.f, 0.f);
    #pragma unroll 8
    for (int l = 0; l < NL; ++l) {
        float a = as[l];
        uint2 p = *(const uint2*)(Xb + (size_t)l * ND + c);
        float2 f0 = __half22float2(*(__half2*)&p.x);
        float2 f1 = __half22float2(*(__half2*)&p.y);
        acc.x = fmaf(a, f0.x, acc.x);
        acc.y = fmaf(a, f0.y, acc.y);
        acc.z = fmaf(a, f1.x, acc.z);
        acc.w = fmaf(a, f1.y, acc.w);
    }
    *(float4*)(ctx + (size_t)b * ND + c) = acc;
}

// ---------------------------------------------------------------------------
extern "C" void kernel_launch(void* const* d_in, const int* in_sizes, int n_in,
                              void* d_out, int out_size)
{
    const float* features = (const float*)d_in[0];
    const float* hidden   = (const float*)d_in[1];
    const float* W1_w     = (const float*)d_in[2];
    const float* W1_b     = (const float*)d_in[3];
    const float* W2_w     = (const float*)d_in[4];
    const float* W2_b     = (const float*)d_in[5];
    const float* V_w      = (const float*)d_in[6];
    // d_in[7] = V_b: unused (softmax shift-invariant)

    float* out  = (float*)d_out;
    float* ctx  = out;
    float* attn = out + (size_t)NB * ND;

    cudaFuncSetAttribute(k2_score_gemm,
                         cudaFuncAttributeMaxDynamicSharedMemorySize, SMEM_K2);

    kprep<<<PREP_GRID, 256>>>(features, hidden, W1_w, W2_w, W2_b);
    k2_score_gemm<<<dim3(NROWS / 128, NU / 128), 128, SMEM_K2>>>(W1_b, V_w);
    k3_softmax<<<NB / 8, 256>>>(attn);
    k4_context<<<NB, 256>>>(attn, ctx);
}

// round 10
// speedup vs baseline: 2.7274x; 1.0145x over previous
#include <cuda_runtime.h>
#include <cuda_fp16.h>
#include <math.h>
#include <stdint.h>

#define NB 512
#define NL 64
#define ND 1024
#define NU 512
#define NROWS (NB * NL)   // 32768 feature rows

// ---------------------------------------------------------------------------
// Device-global scratch (no allocation allowed)
// ---------------------------------------------------------------------------
__device__ __align__(1024) __half g_fa[(size_t)NROWS * ND];    // 64 MB, fp16 features
__device__ __align__(1024) __half g_W1Th[(size_t)NU * ND];     // [N=512][K=1024] fp16
__device__ float g_h[NB * NU];           // hidden @ W2 + b2
__device__ float g_lp[4 * NROWS];        // per-N-block partial logits

// ---------------------------------------------------------------------------
// PTX helpers (sm_80-era: valid on plain sm_103 target)
// ---------------------------------------------------------------------------
__device__ __forceinline__ uint32_t smem_u32(const void* p) {
    uint32_t a;
    asm("{ .reg .u64 t; cvta.to.shared.u64 t, %1; cvt.u32.u64 %0, t; }" : "=r"(a) : "l"(p));
    return a;
}
__device__ __forceinline__ void cp_async16(uint32_t dst, const void* src) {
    asm volatile("cp.async.cg.shared.global [%0], [%1], 16;" :: "r"(dst), "l"(src) : "memory");
}
__device__ __forceinline__ void cp_commit() {
    asm volatile("cp.async.commit_group;" ::: "memory");
}
template <int N> __device__ __forceinline__ void cp_wait() {
    asm volatile("cp.async.wait_group %0;" :: "n"(N) : "memory");
}
__device__ __forceinline__ void ldsm_x4(uint32_t* r, uint32_t addr) {
    asm volatile("ldmatrix.sync.aligned.m8n8.x4.shared.b16 {%0,%1,%2,%3}, [%4];"
                 : "=r"(r[0]), "=r"(r[1]), "=r"(r[2]), "=r"(r[3]) : "r"(addr));
}
__device__ __forceinline__ void mma_f16(float* c, const uint32_t* a, const uint32_t* b) {
    asm volatile(
        "mma.sync.aligned.m16n8k16.row.col.f32.f16.f16.f32 "
        "{%0,%1,%2,%3}, {%4,%5,%6,%7}, {%8,%9}, {%0,%1,%2,%3};"
        : "+f"(c[0]), "+f"(c[1]), "+f"(c[2]), "+f"(c[3])
        : "r"(a[0]), "r"(a[1]), "r"(a[2]), "r"(a[3]), "r"(b[0]), "r"(b[1]));
}

// fast tanh: 1 - 2/(exp2(2*log2e*x)+1); rel err ~1e-6. Saturates correctly.
__device__ __forceinline__ float tanh_fast(float x) {
    float e;
    asm("ex2.approx.f32 %0, %1;" : "=f"(e) : "f"(x * 2.88539008177792681f));
    float r;
    asm("rcp.approx.f32 %0, %1;" : "=f"(r) : "f"(e + 1.0f));
    return 1.0f - 2.0f * r;
}

// ---------------------------------------------------------------------------
// kprep: fused prepass. One launch, three block roles (scheduled in order):
//   blocks [0,64)        : k1  h = hidden @ W2 + b2  (64x64 tiles)
//   blocks [64,576)      : kconvW  W1 -> W1T fp16 transpose
//   blocks [576,33344)   : kconvA  features fp32 -> fp16
// ---------------------------------------------------------------------------
#define PREP_K1   64
#define PREP_KW   512
#define PREP_GRID (PREP_K1 + PREP_KW + 32768)

__global__ __launch_bounds__(256) void kprep(
    const float* __restrict__ features, const float* __restrict__ hidden,
    const float* __restrict__ W1,       const float* __restrict__ W2,
    const float* __restrict__ b2)
{
    __shared__ __align__(16) char sm[8704];
    const int bid = blockIdx.x;
    const int tid = threadIdx.x;

    if (bid >= PREP_K1 + PREP_KW) {
        // ---- kconvA: fp32 -> fp16, 4 elements per thread ----
        size_t i = ((size_t)(bid - PREP_K1 - PREP_KW) * 256 + tid) * 4;
        float4 v = *(const float4*)(features + i);
        __half2 p0 = __floats2half2_rn(v.x, v.y);
        __half2 p1 = __floats2half2_rn(v.z, v.w);
        *(uint2*)((char*)g_fa + i * 2) =
            make_uint2(*(uint32_t*)&p0, *(uint32_t*)&p1);
        return;
    }

    if (bid >= PREP_K1) {
        // ---- kconvW: W1 [K,N] fp32 -> W1T [N,K] fp16 (32x32 tiles) ----
        float (*t)[33] = (float (*)[33])sm;
        int b  = bid - PREP_K1;
        int n0 = (b & 15) * 32, k0 = (b >> 4) * 32;
        int tx = tid & 31, ty = tid >> 5;   // 32 x 8
        #pragma unroll
        for (int i = 0; i < 32; i += 8)
            t[ty + i][tx] = W1[(size_t)(k0 + ty + i) * NU + n0 + tx];
        __syncthreads();
        #pragma unroll
        for (int i = 0; i < 32; i += 8) {
            float v = t[tx][ty + i];                 // = W1[k0+tx][n0+ty+i]
            g_W1Th[(size_t)(n0 + ty + i) * ND + k0 + tx] = __float2half_rn(v);
        }
        return;
    }

    // ---- k1: h = hidden @ W2 + b2 (512x512x512 fp32, 64x64 tiles) ----
    {
        float (*Xs)[64] = (float (*)[64])sm;                 // 16x64
        float (*Ws)[68] = (float (*)[68])(sm + 4096);        // 16x68
        const int tx = tid & 15, ty = tid >> 4;
        const int rowB = (bid & 7) * 64;
        const int nB   = (bid >> 3) * 64;
        float acc[4][4] = {};

        for (int k0 = 0; k0 < NU; k0 += 16) {
            {
                int r = tid >> 2, c4 = (tid & 3) * 4;
                float4 v = *(const float4*)(hidden + (size_t)(rowB + r) * NU + k0 + c4);
                Xs[c4 + 0][r] = v.x; Xs[c4 + 1][r] = v.y;
                Xs[c4 + 2][r] = v.z; Xs[c4 + 3][r] = v.w;
            }
            {
                int k = tid >> 4, c4 = (tid & 15) * 4;
                *(float4*)&Ws[k][c4] = *(const float4*)(W2 + (size_t)(k0 + k) * NU + nB + c4);
            }
            __syncthreads();
            #pragma unroll
            for (int k = 0; k < 16; ++k) {
                float4 a = *(const float4*)&Xs[k][ty * 4];
                float4 b = *(const float4*)&Ws[k][tx * 4];
                float am[4] = {a.x, a.y, a.z, a.w};
                float bn[4] = {b.x, b.y, b.z, b.w};
                #pragma unroll
                for (int i = 0; i < 4; ++i)
                    #pragma unroll
                    for (int j = 0; j < 4; ++j)
                        acc[i][j] = fmaf(am[i], bn[j], acc[i][j]);
            }
            __syncthreads();
        }
        #pragma unroll
        for (int i = 0; i < 4; ++i)
            #pragma unroll
            for (int j = 0; j < 4; ++j)
                g_h[(size_t)(rowB + ty * 4 + i) * NU + nB + tx * 4 + j] =
                    acc[i][j] + b2[nB + tx * 4 + j];
    }
}

// ---------------------------------------------------------------------------
// k2: fp16 mma.sync GEMM, single term (A.Wh), fused epilogue.
// BM=128, BN=128, BK=32. 128 threads (4 warps: 2M x 2N, warp tile 64x64).
// 3-stage cp.async multistage, one barrier per chunk.
// 3 CTAs/SM (smem 64.0KB, regs capped 170) -> 12 warps/SM for latency hiding.
// 80B rows: ldmatrix conflict-free.
// ---------------------------------------------------------------------------
#define ROWB 80
#define TILE_B (128 * ROWB)      // 10240 bytes per tile
#define STG_B  (2 * TILE_B)      // A, Wh
#define STAGES 3
#define NCHUNK (ND / 32)
#define HS_OFF   (STAGES * STG_B)          // 2 x 128 floats
#define VS_OFF   (HS_OFF + 1024)           // 128 floats
#define PART_OFF (VS_OFF + 512)            // 128 x 2 floats
#define SMEM_K2  (PART_OFF + 1024)

__global__ __launch_bounds__(128, 3) void k2_score_gemm(
    const float* __restrict__ b1, const float* __restrict__ Vw)
{
    extern __shared__ __align__(1024) char smem[];
    const uint32_t sb = smem_u32(smem);
    const int tid  = threadIdx.x;
    const int lane = tid & 31, wid = tid >> 5;
    const int wm = wid >> 1, wn = wid & 1;     // 2 x 2 warp grid, 64x64 tiles
    const int rowB = blockIdx.x * 128;
    const int nB   = blockIdx.y * 128;

    float* hs   = (float*)(smem + HS_OFF);    // [2][128]
    float* Vs   = (float*)(smem + VS_OFF);    // [128]
    float* part = (float*)(smem + PART_OFF);  // [128][2]

    // epilogue constants (2 per thread)
    {
        int i0 = tid, i1 = tid + 128;
        hs[i0] = g_h[(size_t)(blockIdx.x * 2) * NU + nB + i0] + b1[nB + i0];
        hs[i1] = g_h[(size_t)(blockIdx.x * 2 + 1) * NU + nB + (i1 - 128)] + b1[nB + (i1 - 128)];
        Vs[tid] = Vw[nB + tid];
    }

    const __half* base0 = g_fa   + (size_t)rowB * ND;
    const __half* base1 = g_W1Th + (size_t)nB   * ND;

    // stage loader: 1024 x 16B chunks, 8 per thread
    auto load_stage = [&](int s, int kc) {
        uint32_t sdst = sb + s * STG_B;
        #pragma unroll
        for (int i = 0; i < 8; ++i) {
            int idx  = tid + i * 128;
            int tile = idx >> 9;               // 512 chunks per tile
            int rem  = idx & 511;
            int row  = rem >> 2, ch = rem & 3;
            const __half* gb = (tile == 0) ? base0 : base1;
            cp_async16(sdst + tile * TILE_B + row * ROWB + ch * 16,
                       gb + (size_t)row * ND + kc * 32 + ch * 8);
        }
        cp_commit();
    };

    // prologue: fill 2 of the 3 stages (chunk c issues chunk c+2)
    load_stage(0, 0);
    load_stage(1, 1);

    float acc[4][8][4] = {};    // [mt 16-row][nt 8-col][vals]

    // precomputed ldmatrix intra-warp offsets
    const int a_row = ((lane >> 3) & 1) * 8 + (lane & 7);
    const int a_ch  = (lane >> 4);
    const int b_row = (lane >> 4) * 8 + (lane & 7);
    const int b_ch  = ((lane >> 3) & 1);

    for (int c = 0; c < NCHUNK; ++c) {
        int s = c % STAGES;
        cp_wait<1>();            // chunk c's stage has landed
        __syncthreads();         // all warps done reading stage (c-1)%3

        // issue next loads NOW (into the stage retired last chunk) so the
        // LDGSTS issue burst overlaps with this chunk's MMA phase
        if (c + 2 < NCHUNK) load_stage((c + 2) % STAGES, c + 2);
        else cp_commit();        // keep wait_group counts consistent

        uint32_t aB  = sb + s * STG_B;
        uint32_t whB = aB + TILE_B;

        #pragma unroll
        for (int kk = 0; kk < 2; ++kk) {
            uint32_t a[4][4], bh[8][2];
            #pragma unroll
            for (int mt = 0; mt < 4; ++mt) {
                int r  = wm * 64 + mt * 16 + a_row;
                int ch = kk * 2 + a_ch;
                ldsm_x4(a[mt], aB + r * ROWB + ch * 16);
            }
            #pragma unroll
            for (int ntp = 0; ntp < 4; ++ntp) {
                int r  = wn * 64 + ntp * 16 + b_row;
                int ch = kk * 2 + b_ch;
                uint32_t t0[4];
                ldsm_x4(t0, whB + r * ROWB + ch * 16);
                bh[ntp*2][0] = t0[0]; bh[ntp*2][1] = t0[1];
                bh[ntp*2+1][0] = t0[2]; bh[ntp*2+1][1] = t0[3];
            }
            #pragma unroll
            for (int mt = 0; mt < 4; ++mt)
                #pragma unroll
                for (int nt = 0; nt < 8; ++nt)
                    mma_f16(acc[mt][nt], a[mt], bh[nt]);
        }
    }

    // Fused epilogue: tanh(acc + b1 + h) . V  -> partial logits
    const int g = lane >> 2, tg4 = lane & 3;
    const int bloc = wm;               // warp tile 64 rows == one batch (L=64)
    #pragma unroll
    for (int mt = 0; mt < 4; ++mt) {
        float s0 = 0.f, s1 = 0.f;
        #pragma unroll
        for (int nt = 0; nt < 8; ++nt) {
            #pragma unroll
            for (int c2 = 0; c2 < 2; ++c2) {
                int col = wn * 64 + nt * 8 + tg4 * 2 + c2;
                float hb = hs[bloc * 128 + col];
                float vw = Vs[col];
                s0 = fmaf(tanh_fast(acc[mt][nt][c2]     + hb), vw, s0);
                s1 = fmaf(tanh_fast(acc[mt][nt][2 + c2] + hb), vw, s1);
            }
        }
        s0 += __shfl_xor_sync(0xFFFFFFFFu, s0, 1);
        s0 += __shfl_xor_sync(0xFFFFFFFFu, s0, 2);
        s1 += __shfl_xor_sync(0xFFFFFFFFu, s1, 1);
        s1 += __shfl_xor_sync(0xFFFFFFFFu, s1, 2);
        if (tg4 == 0) {
            int r0 = wm * 64 + mt * 16 + g;
            part[r0 * 2 + wn]       = s0;
            part[(r0 + 8) * 2 + wn] = s1;
        }
    }
    __syncthreads();
    g_lp[(size_t)blockIdx.y * NROWS + rowB + tid] = part[tid*2] + part[tid*2+1];
}

// ---------------------------------------------------------------------------
// k34: fused softmax (warp 0) + context (all 256 threads). One block/batch.
// ---------------------------------------------------------------------------
__global__ __launch_bounds__(256) void k34_softmax_context(
    float* __restrict__ out_attn, float* __restrict__ ctx)
{
    int b = blockIdx.x;
    __shared__ float as[64];

    if (threadIdx.x < 32) {
        int lane = threadIdx.x;
        float x1 = 0.f, x2 = 0.f;
        #pragma unroll
        for (int p = 0; p < 4; ++p) {
            x1 += g_lp[(size_t)p * NROWS + b * 64 + lane];
            x2 += g_lp[(size_t)p * NROWS + b * 64 + lane + 32];
        }
        float m = fmaxf(x1, x2);
        #pragma unroll
        for (int o = 16; o > 0; o >>= 1)
            m = fmaxf(m, __shfl_xor_sync(0xFFFFFFFFu, m, o));
        float e1 = expf(x1 - m), e2 = expf(x2 - m);
        float s = e1 + e2;
        #pragma unroll
        for (int o = 16; o > 0; o >>= 1)
            s += __shfl_xor_sync(0xFFFFFFFFu, s, o);
        float inv = 1.f / s;
        float a1 = e1 * inv, a2 = e2 * inv;
        as[lane]      = a1;
        as[lane + 32] = a2;
        out_attn[b * 64 + lane]      = a1;
        out_attn[b * 64 + lane + 32] = a2;
    }
    __syncthreads();

    const __half* Xb = g_fa + (size_t)b * NL * ND;
    int c = threadIdx.x * 4;             // 4 halves per thread, 256 thr = 1024
    float4 acc = make_float4(0.f, 0.f, 0.f, 0.f);
    #pragma unroll 8
    for (int l = 0; l < NL; ++l) {
        float a = as[l];
        uint2 p = *(const uint2*)(Xb + (size_t)l * ND + c);
        float2 f0 = __half22float2(*(__half2*)&p.x);
        float2 f1 = __half22float2(*(__half2*)&p.y);
        acc.x = fmaf(a, f0.x, acc.x);
        acc.y = fmaf(a, f0.y, acc.y);
        acc.z = fmaf(a, f1.x, acc.z);
        acc.w = fmaf(a, f1.y, acc.w);
    }
    *(float4*)(ctx + (size_t)b * ND + c) = acc;
}

// ---------------------------------------------------------------------------
extern "C" void kernel_launch(void* const* d_in, const int* in_sizes, int n_in,
                              void* d_out, int out_size)
{
    const float* features = (const float*)d_in[0];
    const float* hidden   = (const float*)d_in[1];
    const float* W1_w     = (const float*)d_in[2];
    const float* W1_b     = (const float*)d_in[3];
    const float* W2_w     = (const float*)d_in[4];
    const float* W2_b     = (const float*)d_in[5];
    const float* V_w      = (const float*)d_in[6];
    // d_in[7] = V_b: unused (softmax shift-invariant)

    float* out  = (float*)d_out;
    float* ctx  = out;
    float* attn = out + (size_t)NB * ND;

    cudaFuncSetAttribute(k2_score_gemm,
                         cudaFuncAttributeMaxDynamicSharedMemorySize, SMEM_K2);

    kprep<<<PREP_GRID, 256>>>(features, hidden, W1_w, W2_w, W2_b);
    k2_score_gemm<<<dim3(NROWS / 128, NU / 128), 128, SMEM_K2>>>(W1_b, V_w);
    k34_softmax_context<<<NB, 256>>>(attn, ctx);
}

// round 11
// speedup vs baseline: 2.7653x; 1.0139x over previous
#include <cuda_runtime.h>
#include <cuda_fp16.h>
#include <math.h>
#include <stdint.h>

#define NB 512
#define NL 64
#define ND 1024
#define NU 512
#define NROWS (NB * NL)   // 32768 feature rows

// ---------------------------------------------------------------------------
// Device-global scratch (no allocation allowed)
// ---------------------------------------------------------------------------
__device__ __align__(1024) __half g_fa[(size_t)NROWS * ND];    // 64 MB, fp16 features
__device__ __align__(1024) __half g_W1Th[(size_t)NU * ND];     // [N=512][K=1024] fp16
__device__ float g_h[NB * NU];           // hidden @ W2 + b2
__device__ float g_lp[4 * NROWS];        // per-N-block partial logits

// ---------------------------------------------------------------------------
// PTX helpers (sm_80-era: valid on plain sm_103 target)
// ---------------------------------------------------------------------------
__device__ __forceinline__ uint32_t smem_u32(const void* p) {
    uint32_t a;
    asm("{ .reg .u64 t; cvta.to.shared.u64 t, %1; cvt.u32.u64 %0, t; }" : "=r"(a) : "l"(p));
    return a;
}
__device__ __forceinline__ void cp_async16(uint32_t dst, const void* src) {
    asm volatile("cp.async.cg.shared.global [%0], [%1], 16;" :: "r"(dst), "l"(src) : "memory");
}
__device__ __forceinline__ void cp_commit() {
    asm volatile("cp.async.commit_group;" ::: "memory");
}
template <int N> __device__ __forceinline__ void cp_wait() {
    asm volatile("cp.async.wait_group %0;" :: "n"(N) : "memory");
}
__device__ __forceinline__ void ldsm_x4(uint32_t* r, uint32_t addr) {
    asm volatile("ldmatrix.sync.aligned.m8n8.x4.shared.b16 {%0,%1,%2,%3}, [%4];"
                 : "=r"(r[0]), "=r"(r[1]), "=r"(r[2]), "=r"(r[3]) : "r"(addr));
}
__device__ __forceinline__ void mma_f16(float* c, const uint32_t* a, const uint32_t* b) {
    asm volatile(
        "mma.sync.aligned.m16n8k16.row.col.f32.f16.f16.f32 "
        "{%0,%1,%2,%3}, {%4,%5,%6,%7}, {%8,%9}, {%0,%1,%2,%3};"
        : "+f"(c[0]), "+f"(c[1]), "+f"(c[2]), "+f"(c[3])
        : "r"(a[0]), "r"(a[1]), "r"(a[2]), "r"(a[3]), "r"(b[0]), "r"(b[1]));
}

// fast tanh: 1 - 2/(exp2(2*log2e*x)+1); rel err ~1e-6. Saturates correctly.
__device__ __forceinline__ float tanh_fast(float x) {
    float e;
    asm("ex2.approx.f32 %0, %1;" : "=f"(e) : "f"(x * 2.88539008177792681f));
    float r;
    asm("rcp.approx.f32 %0, %1;" : "=f"(r) : "f"(e + 1.0f));
    return 1.0f - 2.0f * r;
}

// ---------------------------------------------------------------------------
// kprep: fused prepass. One launch, three block roles (scheduled in order):
//   blocks [0,128)       : k1  h = hidden @ W2 + b2  (32x64 tiles, 128 CTAs)
//   blocks [128,640)     : kconvW  W1 -> W1T fp16 transpose
//   blocks [640,8832)    : kconvA  features fp32 -> fp16 (16 elem/thread, MLP=4)
// ---------------------------------------------------------------------------
#define PREP_K1   128
#define PREP_KW   512
#define PREP_KA   8192
#define PREP_GRID (PREP_K1 + PREP_KW + PREP_KA)

__global__ __launch_bounds__(256) void kprep(
    const float* __restrict__ features, const float* __restrict__ hidden,
    const float* __restrict__ W1,       const float* __restrict__ W2,
    const float* __restrict__ b2)
{
    __shared__ __align__(16) char sm[13056];
    const int bid = blockIdx.x;
    const int tid = threadIdx.x;

    if (bid >= PREP_K1 + PREP_KW) {
        // ---- kconvA: fp32 -> fp16, 16 elements per thread, MLP=4 ----
        size_t base = (size_t)(bid - PREP_K1 - PREP_KW) * 4096;
        #pragma unroll
        for (int s2 = 0; s2 < 4; ++s2) {
            size_t i = base + (size_t)s2 * 1024 + (size_t)tid * 4;
            float4 v = *(const float4*)(features + i);
            __half2 p0 = __floats2half2_rn(v.x, v.y);
            __half2 p1 = __floats2half2_rn(v.z, v.w);
            *(uint2*)((char*)g_fa + i * 2) =
                make_uint2(*(uint32_t*)&p0, *(uint32_t*)&p1);
        }
        return;
    }

    if (bid >= PREP_K1) {
        // ---- kconvW: W1 [K,N] fp32 -> W1T [N,K] fp16 (32x32 tiles) ----
        float (*t)[33] = (float (*)[33])sm;
        int b  = bid - PREP_K1;
        int n0 = (b & 15) * 32, k0 = (b >> 4) * 32;
        int tx = tid & 31, ty = tid >> 5;   // 32 x 8
        #pragma unroll
        for (int i = 0; i < 32; i += 8)
            t[ty + i][tx] = W1[(size_t)(k0 + ty + i) * NU + n0 + tx];
        __syncthreads();
        #pragma unroll
        for (int i = 0; i < 32; i += 8) {
            float v = t[tx][ty + i];                 // = W1[k0+tx][n0+ty+i]
            g_W1Th[(size_t)(n0 + ty + i) * ND + k0 + tx] = __float2half_rn(v);
        }
        return;
    }

    // ---- k1: h = hidden @ W2 + b2 (512x512x512 fp32, 32x64 tiles) ----
    {
        float (*Xs)[33] = (float (*)[33])sm;                 // [32k][32row]
        float (*Ws)[68] = (float (*)[68])(sm + 4224);        // [32k][64col]
        const int tx = tid & 15, ty = tid >> 4;              // 16 x 16
        const int rowB = (bid >> 3) * 32;
        const int nB   = (bid & 7) * 64;
        float acc[2][4] = {};

        for (int k0 = 0; k0 < NU; k0 += 32) {
            {   // X tile 32x32: 1 float4 per thread, stored transposed
                int r = tid >> 3, c4 = (tid & 7) * 4;
                float4 v = *(const float4*)(hidden + (size_t)(rowB + r) * NU + k0 + c4);
                Xs[c4 + 0][r] = v.x; Xs[c4 + 1][r] = v.y;
                Xs[c4 + 2][r] = v.z; Xs[c4 + 3][r] = v.w;
            }
            #pragma unroll
            for (int p = 0; p < 2; ++p) {   // W tile 32x64: 2 float4 per thread
                int k = (tid >> 4) + p * 16, c4 = (tid & 15) * 4;
                *(float4*)&Ws[k][c4] =
                    *(const float4*)(W2 + (size_t)(k0 + k) * NU + nB + c4);
            }
            __syncthreads();
            #pragma unroll
            for (int k = 0; k < 32; ++k) {
                float a0 = Xs[k][ty * 2], a1 = Xs[k][ty * 2 + 1];
                float4 b = *(const float4*)&Ws[k][tx * 4];
                float bn[4] = {b.x, b.y, b.z, b.w};
                #pragma unroll
                for (int j = 0; j < 4; ++j) {
                    acc[0][j] = fmaf(a0, bn[j], acc[0][j]);
                    acc[1][j] = fmaf(a1, bn[j], acc[1][j]);
                }
            }
            __syncthreads();
        }
        #pragma unroll
        for (int i = 0; i < 2; ++i)
            #pragma unroll
            for (int j = 0; j < 4; ++j)
                g_h[(size_t)(rowB + ty * 2 + i) * NU + nB + tx * 4 + j] =
                    acc[i][j] + b2[nB + tx * 4 + j];
    }
}

// ---------------------------------------------------------------------------
// k2: fp16 mma.sync GEMM, single term (A.Wh), fused epilogue.
// BM=128, BN=128, BK=32. 128 threads (4 warps: 2M x 2N, warp tile 64x64).
// 3-stage cp.async multistage, one barrier per chunk.
// 3 CTAs/SM (smem 64.0KB, regs capped 170) -> 12 warps/SM for latency hiding.
// 80B rows: ldmatrix conflict-free.
// ---------------------------------------------------------------------------
#define ROWB 80
#define TILE_B (128 * ROWB)      // 10240 bytes per tile
#define STG_B  (2 * TILE_B)      // A, Wh
#define STAGES 3
#define NCHUNK (ND / 32)
#define HS_OFF   (STAGES * STG_B)          // 2 x 128 floats
#define VS_OFF   (HS_OFF + 1024)           // 128 floats
#define PART_OFF (VS_OFF + 512)            // 128 x 2 floats
#define SMEM_K2  (PART_OFF + 1024)

__global__ __launch_bounds__(128, 3) void k2_score_gemm(
    const float* __restrict__ b1, const float* __restrict__ Vw)
{
    extern __shared__ __align__(1024) char smem[];
    const uint32_t sb = smem_u32(smem);
    const int tid  = threadIdx.x;
    const int lane = tid & 31, wid = tid >> 5;
    const int wm = wid >> 1, wn = wid & 1;     // 2 x 2 warp grid, 64x64 tiles
    const int rowB = blockIdx.x * 128;
    const int nB   = blockIdx.y * 128;

    float* hs   = (float*)(smem + HS_OFF);    // [2][128]
    float* Vs   = (float*)(smem + VS_OFF);    // [128]
    float* part = (float*)(smem + PART_OFF);  // [128][2]

    // epilogue constants (2 per thread)
    {
        int i0 = tid, i1 = tid + 128;
        hs[i0] = g_h[(size_t)(blockIdx.x * 2) * NU + nB + i0] + b1[nB + i0];
        hs[i1] = g_h[(size_t)(blockIdx.x * 2 + 1) * NU + nB + (i1 - 128)] + b1[nB + (i1 - 128)];
        Vs[tid] = Vw[nB + tid];
    }

    const __half* base0 = g_fa   + (size_t)rowB * ND;
    const __half* base1 = g_W1Th + (size_t)nB   * ND;

    // stage loader: 1024 x 16B chunks, 8 per thread
    auto load_stage = [&](int s, int kc) {
        uint32_t sdst = sb + s * STG_B;
        #pragma unroll
        for (int i = 0; i < 8; ++i) {
            int idx  = tid + i * 128;
            int tile = idx >> 9;               // 512 chunks per tile
            int rem  = idx & 511;
            int row  = rem >> 2, ch = rem & 3;
            const __half* gb = (tile == 0) ? base0 : base1;
            cp_async16(sdst + tile * TILE_B + row * ROWB + ch * 16,
                       gb + (size_t)row * ND + kc * 32 + ch * 8);
        }
        cp_commit();
    };

    // prologue: fill 2 of the 3 stages (chunk c issues chunk c+2)
    load_stage(0, 0);
    load_stage(1, 1);

    float acc[4][8][4] = {};    // [mt 16-row][nt 8-col][vals]

    // precomputed ldmatrix intra-warp offsets
    const int a_row = ((lane >> 3) & 1) * 8 + (lane & 7);
    const int a_ch  = (lane >> 4);
    const int b_row = (lane >> 4) * 8 + (lane & 7);
    const int b_ch  = ((lane >> 3) & 1);

    for (int c = 0; c < NCHUNK; ++c) {
        int s = c % STAGES;
        cp_wait<1>();            // chunk c's stage has landed
        __syncthreads();         // all warps done reading stage (c-1)%3

        // issue next loads NOW (into the stage retired last chunk) so the
        // LDGSTS issue burst overlaps with this chunk's MMA phase
        if (c + 2 < NCHUNK) load_stage((c + 2) % STAGES, c + 2);
        else cp_commit();        // keep wait_group counts consistent

        uint32_t aB  = sb + s * STG_B;
        uint32_t whB = aB + TILE_B;

        #pragma unroll
        for (int kk = 0; kk < 2; ++kk) {
            uint32_t a[4][4], bh[8][2];
            #pragma unroll
            for (int mt = 0; mt < 4; ++mt) {
                int r  = wm * 64 + mt * 16 + a_row;
                int ch = kk * 2 + a_ch;
                ldsm_x4(a[mt], aB + r * ROWB + ch * 16);
            }
            #pragma unroll
            for (int ntp = 0; ntp < 4; ++ntp) {
                int r  = wn * 64 + ntp * 16 + b_row;
                int ch = kk * 2 + b_ch;
                uint32_t t0[4];
                ldsm_x4(t0, whB + r * ROWB + ch * 16);
                bh[ntp*2][0] = t0[0]; bh[ntp*2][1] = t0[1];
                bh[ntp*2+1][0] = t0[2]; bh[ntp*2+1][1] = t0[3];
            }
            #pragma unroll
            for (int mt = 0; mt < 4; ++mt)
                #pragma unroll
                for (int nt = 0; nt < 8; ++nt)
                    mma_f16(acc[mt][nt], a[mt], bh[nt]);
        }
    }

    // Fused epilogue: tanh(acc + b1 + h) . V  -> partial logits
    const int g = lane >> 2, tg4 = lane & 3;
    const int bloc = wm;               // warp tile 64 rows == one batch (L=64)
    #pragma unroll
    for (int mt = 0; mt < 4; ++mt) {
        float s0 = 0.f, s1 = 0.f;
        #pragma unroll
        for (int nt = 0; nt < 8; ++nt) {
            #pragma unroll
            for (int c2 = 0; c2 < 2; ++c2) {
                int col = wn * 64 + nt * 8 + tg4 * 2 + c2;
                float hb = hs[bloc * 128 + col];
                float vw = Vs[col];
                s0 = fmaf(tanh_fast(acc[mt][nt][c2]     + hb), vw, s0);
                s1 = fmaf(tanh_fast(acc[mt][nt][2 + c2] + hb), vw, s1);
            }
        }
        s0 += __shfl_xor_sync(0xFFFFFFFFu, s0, 1);
        s0 += __shfl_xor_sync(0xFFFFFFFFu, s0, 2);
        s1 += __shfl_xor_sync(0xFFFFFFFFu, s1, 1);
        s1 += __shfl_xor_sync(0xFFFFFFFFu, s1, 2);
        if (tg4 == 0) {
            int r0 = wm * 64 + mt * 16 + g;
            part[r0 * 2 + wn]       = s0;
            part[(r0 + 8) * 2 + wn] = s1;
        }
    }
    __syncthreads();
    g_lp[(size_t)blockIdx.y * NROWS + rowB + tid] = part[tid*2] + part[tid*2+1];
}

// ---------------------------------------------------------------------------
// k34: fused softmax (warp 0) + context (all 256 threads). One block/batch.
// ---------------------------------------------------------------------------
__global__ __launch_bounds__(256) void k34_softmax_context(
    float* __restrict__ out_attn, float* __restrict__ ctx)
{
    int b = blockIdx.x;
    __shared__ float as[64];

    if (threadIdx.x < 32) {
        int lane = threadIdx.x;
        float x1 = 0.f, x2 = 0.f;
        #pragma unroll
        for (int p = 0; p < 4; ++p) {
            x1 += g_lp[(size_t)p * NROWS + b * 64 + lane];
            x2 += g_lp[(size_t)p * NROWS + b * 64 + lane + 32];
        }
        float m = fmaxf(x1, x2);
        #pragma unroll
        for (int o = 16; o > 0; o >>= 1)
            m = fmaxf(m, __shfl_xor_sync(0xFFFFFFFFu, m, o));
        float e1 = expf(x1 - m), e2 = expf(x2 - m);
        float s = e1 + e2;
        #pragma unroll
        for (int o = 16; o > 0; o >>= 1)
            s += __shfl_xor_sync(0xFFFFFFFFu, s, o);
        float inv = 1.f / s;
        float a1 = e1 * inv, a2 = e2 * inv;
        as[lane]      = a1;
        as[lane + 32] = a2;
        out_attn[b * 64 + lane]      = a1;
        out_attn[b * 64 + lane + 32] = a2;
    }
    __syncthreads();

    const __half* Xb = g_fa + (size_t)b * NL * ND;
    int c = threadIdx.x * 4;             // 4 halves per thread, 256 thr = 1024
    float4 acc = make_float4(0.f, 0.f, 0.f, 0.f);
    #pragma unroll 8
    for (int l = 0; l < NL; ++l) {
        float a = as[l];
        uint2 p = *(const uint2*)(Xb + (size_t)l * ND + c);
        float2 f0 = __half22float2(*(__half2*)&p.x);
        float2 f1 = __half22float2(*(__half2*)&p.y);
        acc.x = fmaf(a, f0.x, acc.x);
        acc.y = fmaf(a, f0.y, acc.y);
        acc.z = fmaf(a, f1.x, acc.z);
        acc.w = fmaf(a, f1.y, acc.w);
    }
    *(float4*)(ctx + (size_t)b * ND + c) = acc;
}

// ---------------------------------------------------------------------------
extern "C" void kernel_launch(void* const* d_in, const int* in_sizes, int n_in,
                              void* d_out, int out_size)
{
    const float* features = (const float*)d_in[0];
    const float* hidden   = (const float*)d_in[1];
    const float* W1_w     = (const float*)d_in[2];
    const float* W1_b     = (const float*)d_in[3];
    const float* W2_w     = (const float*)d_in[4];
    const float* W2_b     = (const float*)d_in[5];
    const float* V_w      = (const float*)d_in[6];
    // d_in[7] = V_b: unused (softmax shift-invariant)

    float* out  = (float*)d_out;
    float* ctx  = out;
    float* attn = out + (size_t)NB * ND;

    cudaFuncSetAttribute(k2_score_gemm,
                         cudaFuncAttributeMaxDynamicSharedMemorySize, SMEM_K2);

    kprep<<<PREP_GRID, 256>>>(features, hidden, W1_w, W2_w, W2_b);
    k2_score_gemm<<<dim3(NROWS / 128, NU / 128), 128, SMEM_K2>>>(W1_b, V_w);
    k34_softmax_context<<<NB, 256>>>(attn, ctx);
}